// round 12
// baseline (speedup 1.0000x reference)
#include <cuda_runtime.h>
#include <cstdint>
#include <cstddef>

#define TT 256
#define BB 64
#define HH 512
#define G6 3072
#define G5 2560
#define LAYER_W_STRIDE (512*3072 + 512*2560)   /* 2883584 */
#define WHH_OFF (512*3072)                      /* 1572864 */
#define NCTA 128

// smem layout for lstm kernel (floats)
#define OFF_W 0
#define OFF_H 10240
#define OFF_R 43008
#define OFF_MBAR_BYTES ((10240 + 32768 + 10752) * 4)   /* 215040 */
#define SMEM_LSTM (OFF_MBAR_BYTES + 64)

// ---------------- device scratch (static, no runtime alloc) ----------------
__device__ float g_xt[(size_t)TT*HH*BB];          // layer input  [t][k][b]
__device__ float g_yt[(size_t)TT*HH*BB];          // layer output [t][k][b]
__device__ float g_xr[(size_t)TT*HH*BB];          // reversed input
__device__ float g_xi[(size_t)TT*G6*BB];          // xi [t][g][b]
__device__ float g_h0[HH*BB];
__device__ float g_h1[HH*BB];
__device__ float g_wt[(size_t)4*G5*HH];           // W_hh packed [l][hid*5+g][k]
__device__ unsigned g_cnt[4];                     // per-group monotonic counters

// ---------------- helpers ----------------
__device__ __forceinline__ float2 ffma2(float2 a, float2 b, float2 c) {
    union U { float2 f; unsigned long long u; };
    U A, B, C, D;
    A.f = a; B.f = b; C.f = c;
    asm("fma.rn.f32x2 %0, %1, %2, %3;" : "=l"(D.u) : "l"(A.u), "l"(B.u), "l"(C.u));
    return D.f;
}
__device__ __forceinline__ float sigmoidf_(float x) {
    return 1.0f / (1.0f + __expf(-x));
}
__device__ __forceinline__ void red_add_release_gpu(unsigned* p, unsigned v) {
    asm volatile("red.release.gpu.add.u32 [%0], %1;" :: "l"(p), "r"(v) : "memory");
}
__device__ __forceinline__ unsigned ld_acquire_gpu(const unsigned* p) {
    unsigned v;
    asm volatile("ld.acquire.gpu.u32 %0, [%1];" : "=r"(v) : "l"(p) : "memory");
    return v;
}
__device__ __forceinline__ unsigned smem_u32(const void* p) {
    unsigned a;
    asm("{ .reg .u64 t; cvta.to.shared.u64 t, %1; cvt.u32.u64 %0, t; }"
        : "=r"(a) : "l"(p));
    return a;
}
__device__ __forceinline__ void mbar_init(unsigned a, unsigned cnt) {
    asm volatile("mbarrier.init.shared.b64 [%0], %1;" :: "r"(a), "r"(cnt) : "memory");
}
__device__ __forceinline__ void mbar_expect_tx(unsigned a, unsigned bytes) {
    asm volatile("mbarrier.arrive.expect_tx.shared.b64 _, [%0], %1;"
                 :: "r"(a), "r"(bytes) : "memory");
}
__device__ __forceinline__ void bulk_g2s(unsigned dst, const void* src,
                                         unsigned bytes, unsigned mbar) {
    asm volatile("cp.async.bulk.shared::cluster.global.mbarrier::complete_tx::bytes "
                 "[%0], [%1], %2, [%3];"
                 :: "r"(dst), "l"(src), "r"(bytes), "r"(mbar) : "memory");
}
__device__ __forceinline__ void mbar_wait_parity(unsigned a, unsigned phase) {
    unsigned done;
    asm volatile(
        "{\n\t.reg .pred p;\n\t"
        "mbarrier.try_wait.parity.acquire.cta.shared::cta.b64 p, [%1], %2;\n\t"
        "selp.b32 %0, 1, 0, p;\n\t}"
        : "=r"(done) : "r"(a), "r"(phase) : "memory");
    if (!done) {
        asm volatile(
            "{\n\t.reg .pred P1;\n\t"
            "WL_%=:\n\t"
            "mbarrier.try_wait.parity.acquire.cta.shared::cta.b64 P1, [%0], %1, 0x989680;\n\t"
            "@P1 bra.uni WD_%=;\n\t"
            "bra.uni WL_%=;\n\t"
            "WD_%=:\n\t}"
            :: "r"(a), "r"(phase) : "memory");
    }
}

// ---------------- prep: (B,T,K) -> [t][k][b], masked ----------------
__global__ void prep_kernel(const float* __restrict__ in, const int* __restrict__ len) {
    int idx = blockIdx.x * blockDim.x + threadIdx.x;
    if (idx >= TT*HH*BB) return;
    int b = idx & 63;
    int k = (idx >> 6) & 511;
    int t = idx >> 15;
    float v = 0.f;
    if (t < len[b]) v = in[((size_t)b*TT + t)*HH + k];
    g_xt[idx] = v;
}

// ---------------- reverse gather ----------------
__global__ void reverse_kernel(const float* __restrict__ xt, float* __restrict__ xr,
                               const int* __restrict__ len) {
    int idx = blockIdx.x * blockDim.x + threadIdx.x;
    if (idx >= TT*HH*BB) return;
    int b = idx & 63;
    int k = (idx >> 6) & 511;
    int t = idx >> 15;
    int L = len[b];
    int tp = (t < L) ? (L - 1 - t) : t;
    xr[idx] = xt[((size_t)tp*HH + k)*BB + b];
}

// ---------------- pack W_hh[k][g*512+hid] -> wt[l][(hid*5+g)][k] ----------------
__global__ void packw_kernel(const float* __restrict__ weight) {
    int idx = blockIdx.x * blockDim.x + threadIdx.x;
    if (idx >= 4*HH*G5) return;
    int col = idx % G5;
    int k   = (idx / G5) % HH;
    int l   = idx / (G5*HH);
    int hid = col & 511, g = col >> 9;
    float v = weight[(size_t)l*LAYER_W_STRIDE + WHH_OFF + (size_t)k*G5 + col];
    g_wt[(size_t)l*(G5*HH) + (size_t)((hid*5 + g) << 9) + k] = v;
}

// ---------------- xi GEMM (SIMT, unchanged passing version) ----------------
__device__ __forceinline__ int bskew(int c) { return c + ((c >> 5) << 2); }

__global__ __launch_bounds__(256, 2)
void gemm_xi_kernel(const float* __restrict__ X, const float* __restrict__ W,
                    float* __restrict__ XI)
{
    __shared__ float As[8][128];
    __shared__ float Bs[8][144];
    int tid = threadIdx.x;
    int mBase = blockIdx.x * 128;
    int gBase = blockIdx.y * 128;

    float2 acc[8][4];
    #pragma unroll
    for (int i = 0; i < 8; i++)
        #pragma unroll
        for (int j = 0; j < 4; j++) acc[i][j] = make_float2(0.f, 0.f);

    int sk  = tid >> 5;
    int sc4 = (tid & 31) * 4;
    int ty8 = (tid >> 4) * 8;
    int tx8 = (tid & 15) * 8;

    int m4 = mBase + sc4;
    const float* bsrc = X + ((size_t)(m4 >> 6) * HH) * BB + (m4 & 63);
    const float* asrc = W + gBase + sc4;
    int bsw = bskew(sc4);
    int c0 = bskew(tx8), c1 = bskew(tx8 + 4);

    for (int k0 = 0; k0 < 512; k0 += 8) {
        float4 av = *(const float4*)(asrc + (size_t)(k0 + sk)*G6);
        float4 bv = *(const float4*)(bsrc + (size_t)(k0 + sk)*BB);
        *(float4*)&As[sk][sc4] = av;
        *(float4*)&Bs[sk][bsw] = bv;
        __syncthreads();
        #pragma unroll
        for (int kk = 0; kk < 8; kk++) {
            float4 a0 = *(float4*)&As[kk][ty8];
            float4 a1 = *(float4*)&As[kk][ty8+4];
            float4 b0 = *(float4*)&Bs[kk][c0];
            float4 b1 = *(float4*)&Bs[kk][c1];
            float  ar[8] = {a0.x,a0.y,a0.z,a0.w,a1.x,a1.y,a1.z,a1.w};
            float2 br[4] = {make_float2(b0.x,b0.y), make_float2(b0.z,b0.w),
                            make_float2(b1.x,b1.y), make_float2(b1.z,b1.w)};
            #pragma unroll
            for (int i = 0; i < 8; i++) {
                float2 ad = make_float2(ar[i], ar[i]);
                #pragma unroll
                for (int jp = 0; jp < 4; jp++)
                    acc[i][jp] = ffma2(ad, br[jp], acc[i][jp]);
            }
        }
        __syncthreads();
    }

    int m0 = mBase + tx8;
    int t  = m0 >> 6;
    int b0 = m0 & 63;
    #pragma unroll
    for (int i = 0; i < 8; i++) {
        float* o = XI + ((size_t)t*G6 + gBase + ty8 + i)*BB + b0;
        *(float4*)(o)     = make_float4(acc[i][0].x, acc[i][0].y, acc[i][1].x, acc[i][1].y);
        *(float4*)(o + 4) = make_float4(acc[i][2].x, acc[i][2].y, acc[i][3].x, acc[i][3].y);
    }
}

// ---------------- persistent per-layer recurrence ----------------
// 128 CTAs x 288 thr. Changes vs R10:
//  - 4 independent staging lanes (tid 256..259), one per chunk/producer group:
//    each polls its own cnt and issues its cp.async.bulk in arrival order.
//  - per-warp release (syncwarp + lane0 red.release, 8/CTA) replaces the
//    CTA-wide sync B + single release; one __syncthreads per step.
__global__ __launch_bounds__(288)
void lstm_layer_kernel(const float* __restrict__ xi_base,
                       const float* __restrict__ wt,
                       const float* __restrict__ bias,
                       const int*   __restrict__ len,
                       float* __restrict__ hbuf0,
                       float* __restrict__ hbuf1,
                       float* __restrict__ y,
                       int rev)
{
    extern __shared__ float smf[];
    int tid = threadIdx.x;
    int hid0 = blockIdx.x * 4;
    int grp  = blockIdx.x >> 5;

    unsigned smbase = smem_u32(smf);
    unsigned mbar0  = smbase + OFF_MBAR_BYTES;
    unsigned hdst0  = smbase + OFF_H * 4;

    int w8 = tid >> 5;
    int bp = tid & 31;
    int hl_o = tid >> 6;
    int b_o  = tid & 63;
    int hid_o = hid0 + (hl_o & 3);

    if (tid < 256) {
        const float4* ws = (const float4*)(wt + (size_t)hid0 * 5 * 512);
        float4* wd = (float4*)(smf + OFF_W);
        #pragma unroll
        for (int i = 0; i < 10; i++) wd[tid + i*256] = ws[tid + i*256];
    }
    if (tid == 256) {
        #pragma unroll
        for (int c = 0; c < 4; c++) mbar_init(mbar0 + 8*c, 1);
        asm volatile("fence.proxy.async.shared::cta;" ::: "memory");
    }

    float bval[5] = {0.f, 0.f, 0.f, 0.f, 0.f};
    int L = 0;
    float xiv[6] = {0.f, 0.f, 0.f, 0.f, 0.f, 0.f};
    if (tid < 256) {
        #pragma unroll
        for (int g = 0; g < 5; g++) bval[g] = bias[g*512 + hid_o];
        L = len[b_o];
        #pragma unroll
        for (int g = 0; g < 6; g++)
            xiv[g] = __ldcs(xi_base + (size_t)(g*512 + hid_o)*BB + b_o);
    }
    float c = 0.0f;

    const float* hin  = hbuf0;
    float*       hout = hbuf1;

    __syncthreads();                      // weights + mbar init visible

    // stage step 0 (h[-1] = zeros, no producers to wait for): 4 lanes
    if (tid >= 256 && tid < 260) {
        int ch = tid - 256;
        mbar_expect_tx(mbar0 + 8*ch, 32768u);
        bulk_g2s(hdst0 + (unsigned)ch*32768u, hin + ch*8192, 32768u, mbar0 + 8*ch);
    }

    for (int s = 0; s < TT; s++) {
        unsigned phase = (unsigned)(s & 1);

        if (tid < 256) {
            float2 acc[20];
            #pragma unroll
            for (int q = 0; q < 20; q++) acc[q] = make_float2(0.f, 0.f);

            #pragma unroll
            for (int ch = 0; ch < 4; ch++) {
                mbar_wait_parity(mbar0 + 8*ch, phase);
                const float* shh = smf + OFF_H + ch*8192 + 2*bp;
                const float* shw = smf + OFF_W + ch*128 + w8*16;
                #pragma unroll
                for (int k4 = 0; k4 < 16; k4 += 4) {
                    int kb = (w8*16 + k4) * 64;
                    float2 hv0 = *(const float2*)(shh + kb);
                    float2 hv1 = *(const float2*)(shh + kb + 64);
                    float2 hv2 = *(const float2*)(shh + kb + 128);
                    float2 hv3 = *(const float2*)(shh + kb + 192);
                    #pragma unroll
                    for (int q = 0; q < 20; q++) {
                        float4 w4 = *(const float4*)(shw + q*512 + k4);
                        acc[q] = ffma2(hv0, make_float2(w4.x, w4.x), acc[q]);
                        acc[q] = ffma2(hv1, make_float2(w4.y, w4.y), acc[q]);
                        acc[q] = ffma2(hv2, make_float2(w4.z, w4.z), acc[q]);
                        acc[q] = ffma2(hv3, make_float2(w4.w, w4.w), acc[q]);
                    }
                }
            }

            float* rb = smf + OFF_R + (w8*32 + bp)*42;
            #pragma unroll
            for (int q = 0; q < 20; q++) *(float2*)(rb + 2*q) = acc[q];
        }
        __syncthreads();   // sync A: partials ready AND all smem-h reads done

        if (tid < 256) {
            float gv[5];
            #pragma unroll
            for (int g = 0; g < 5; g++) gv[g] = xiv[g] + bval[g];
            const float* rbase = smf + OFF_R + (b_o >> 1)*42 + (b_o & 1);
            #pragma unroll
            for (int w2 = 0; w2 < 8; w2++) {
                const float* p = rbase + w2*32*42;
                #pragma unroll
                for (int g = 0; g < 5; g++)
                    gv[g] += p[(hl_o*5 + g)*2];
            }

            float ig = sigmoidf_(gv[0]);
            float fg = sigmoidf_(gv[1]);
            float gc = tanhf(gv[2]);
            float og = sigmoidf_(gv[3]);
            float rg = sigmoidf_(gv[4]);
            float lin = xiv[5];

            float cn, hn;
            if (s < L) {
                cn = fg*c + ig*gc;
                hn = rg*(og*tanhf(cn)) + (1.f - rg)*lin;
            } else {
                cn = 0.f; hn = 0.f;
            }
            c = cn;
            hout[hid_o*BB + b_o] = hn;                // coalesced
            int dst = rev ? ((s < L) ? (L - 1 - s) : s) : s;

            if (s != TT-1) {
                __syncwarp();                         // warp's hout STGs done
                if ((tid & 31) == 0)
                    red_add_release_gpu(&g_cnt[grp], 1u);
                // release shadow: y store + next-step xi prefetch
                y[((size_t)dst*HH + hid_o)*BB + b_o] = hn;
                const float* xs = xi_base + (size_t)(s+1)*G6*BB;
                #pragma unroll
                for (int g = 0; g < 6; g++)
                    xiv[g] = __ldcs(xs + (size_t)(g*512 + hid_o)*BB + b_o);
            } else {
                y[((size_t)dst*HH + hid_o)*BB + b_o] = hn;
            }
        } else if (tid < 260 && s != TT-1) {
            // staging lane for chunk ch: poll its producer group, issue TMA.
            // Safe after sync A (all local smem-h reads of step s complete).
            int ch = tid - 256;
            unsigned target = 256u * (unsigned)(s + 1);   // 32 CTAs x 8 warps
            while (ld_acquire_gpu(&g_cnt[ch]) < target) __nanosleep(32);
            mbar_expect_tx(mbar0 + 8*ch, 32768u);
            bulk_g2s(hdst0 + (unsigned)ch*32768u, hout + ch*8192, 32768u,
                     mbar0 + 8*ch);
        }

        const float* tmp = hin; hin = hout; hout = (float*)tmp;
    }
}

// ---------------- final: [t][k][b] -> (B,T,K) ----------------
__global__ void out_kernel(const float* __restrict__ xt, float* __restrict__ out) {
    int idx = blockIdx.x * blockDim.x + threadIdx.x;
    if (idx >= TT*HH*BB) return;
    int k = idx & 511;
    int t = (idx >> 9) & 255;
    int b = idx >> 17;
    out[idx] = xt[((size_t)t*HH + k)*BB + b];
}

// ---------------- launch ----------------
extern "C" void kernel_launch(void* const* d_in, const int* in_sizes, int n_in,
                              void* d_out, int out_size)
{
    const float* inputs = nullptr;
    const float* weight = nullptr;
    const float* biasp  = nullptr;
    const int*   len    = nullptr;
    for (int i = 0; i < n_in; i++) {
        switch (in_sizes[i]) {
            case TT*BB*HH:  inputs = (const float*)d_in[i]; break;  // 8388608
            case 11534336:  weight = (const float*)d_in[i]; break;
            case 4*G5:      biasp  = (const float*)d_in[i]; break;  // 10240
            case BB:        len    = (const int*)  d_in[i]; break;  // 64
        }
    }

    float *pxt, *pyt, *pxr, *pxi, *ph0, *ph1, *pwt;
    unsigned* pcnt;
    cudaGetSymbolAddress((void**)&pxt, g_xt);
    cudaGetSymbolAddress((void**)&pyt, g_yt);
    cudaGetSymbolAddress((void**)&pxr, g_xr);
    cudaGetSymbolAddress((void**)&pxi, g_xi);
    cudaGetSymbolAddress((void**)&ph0, g_h0);
    cudaGetSymbolAddress((void**)&ph1, g_h1);
    cudaGetSymbolAddress((void**)&pwt, g_wt);
    cudaGetSymbolAddress((void**)&pcnt, g_cnt);

    cudaFuncSetAttribute(lstm_layer_kernel,
                         cudaFuncAttributeMaxDynamicSharedMemorySize, SMEM_LSTM);

    prep_kernel<<<(TT*HH*BB + 255)/256, 256>>>(inputs, len);
    packw_kernel<<<(4*HH*G5 + 255)/256, 256>>>(weight);

    float* xin  = pxt;
    float* yout = pyt;
    for (int l = 0; l < 4; l++) {
        int rev = l & 1;
        const float* gsrc = xin;
        if (rev) {
            reverse_kernel<<<(TT*HH*BB + 255)/256, 256>>>(xin, pxr, len);
            gsrc = pxr;
        }
        gemm_xi_kernel<<<dim3(128, 24), 256>>>(
            gsrc, weight + (size_t)l*LAYER_W_STRIDE, pxi);
        cudaMemsetAsync(ph0, 0, (size_t)HH*BB*sizeof(float));
        cudaMemsetAsync(pcnt, 0, 4*sizeof(unsigned));
        lstm_layer_kernel<<<NCTA, 288, SMEM_LSTM>>>(
            pxi, pwt + (size_t)l*G5*HH, biasp + (size_t)l*G5,
            len, ph0, ph1, yout, rev);
        float* tmp = xin; xin = yout; yout = tmp;
    }
    out_kernel<<<(TT*HH*BB + 255)/256, 256>>>(xin, (float*)d_out);
}

// round 13
// speedup vs baseline: 1.3913x; 1.3913x over previous
#include <cuda_runtime.h>
#include <cuda_bf16.h>
#include <cstdint>
#include <cstddef>

#define TT 256
#define BB 64
#define HH 512
#define G6 3072
#define G5 2560
#define LAYER_W_STRIDE (512*3072 + 512*2560)   /* 2883584 */
#define WHH_OFF (512*3072)                      /* 1572864 */
#define NCTA 128

// smem layout for lstm kernel (floats)
#define OFF_W 0
#define OFF_H 10240
#define OFF_R 43008
#define OFF_MBAR_BYTES ((10240 + 32768 + 10752) * 4)   /* 215040 */
#define SMEM_LSTM (OFF_MBAR_BYTES + 64)

// gemm smem: 2 stages x (Ah|Al|Bh|Bl) x 16KB = 131072 B + mbars
#define SMEM_GMM (131072 + 64)

// ---------------- device scratch (static, no runtime alloc) ----------------
__device__ float g_xt[(size_t)TT*HH*BB];          // layer input  [t][k][b]
__device__ float g_yt[(size_t)TT*HH*BB];          // layer output [t][k][b]
__device__ float g_xi[(size_t)TT*G6*BB];          // xi [t][g][b]
__device__ float g_h0[HH*BB];
__device__ float g_h1[HH*BB];
__device__ float g_wt[(size_t)4*G5*HH];           // W_hh packed [l][hid*5+g][k]
__device__ unsigned g_cnt[4];                     // per-group monotonic counters
// GEMM operand tiles (pre-swizzled SW128 blocked-atom, bf16 split)
__device__ uint4 g_wbh[(size_t)4*24*8192];        // W_ih^T hi: [l][ntile][128n x 512k]
__device__ uint4 g_wbl[(size_t)4*24*8192];        // W_ih^T lo
__device__ uint4 g_xah[(size_t)128*8192];         // X hi: [mtile][128m x 512k]
__device__ uint4 g_xal[(size_t)128*8192];         // X lo

// ---------------- helpers ----------------
__device__ __forceinline__ float2 ffma2(float2 a, float2 b, float2 c) {
    union U { float2 f; unsigned long long u; };
    U A, B, C, D;
    A.f = a; B.f = b; C.f = c;
    asm("fma.rn.f32x2 %0, %1, %2, %3;" : "=l"(D.u) : "l"(A.u), "l"(B.u), "l"(C.u));
    return D.f;
}
__device__ __forceinline__ float sigmoidf_(float x) {
    return 1.0f / (1.0f + __expf(-x));
}
__device__ __forceinline__ void red_add_release_gpu(unsigned* p, unsigned v) {
    asm volatile("red.release.gpu.add.u32 [%0], %1;" :: "l"(p), "r"(v) : "memory");
}
__device__ __forceinline__ unsigned ld_acquire_gpu(const unsigned* p) {
    unsigned v;
    asm volatile("ld.acquire.gpu.u32 %0, [%1];" : "=r"(v) : "l"(p) : "memory");
    return v;
}
__device__ __forceinline__ unsigned smem_u32(const void* p) {
    unsigned a;
    asm("{ .reg .u64 t; cvta.to.shared.u64 t, %1; cvt.u32.u64 %0, t; }"
        : "=r"(a) : "l"(p));
    return a;
}
__device__ __forceinline__ void mbar_init(unsigned a, unsigned cnt) {
    asm volatile("mbarrier.init.shared.b64 [%0], %1;" :: "r"(a), "r"(cnt) : "memory");
}
__device__ __forceinline__ void mbar_expect_tx(unsigned a, unsigned bytes) {
    asm volatile("mbarrier.arrive.expect_tx.shared.b64 _, [%0], %1;"
                 :: "r"(a), "r"(bytes) : "memory");
}
__device__ __forceinline__ void bulk_g2s(unsigned dst, const void* src,
                                         unsigned bytes, unsigned mbar) {
    asm volatile("cp.async.bulk.shared::cluster.global.mbarrier::complete_tx::bytes "
                 "[%0], [%1], %2, [%3];"
                 :: "r"(dst), "l"(src), "r"(bytes), "r"(mbar) : "memory");
}
__device__ __forceinline__ void mbar_wait_parity(unsigned a, unsigned phase) {
    unsigned done;
    asm volatile(
        "{\n\t.reg .pred p;\n\t"
        "mbarrier.try_wait.parity.acquire.cta.shared::cta.b64 p, [%1], %2;\n\t"
        "selp.b32 %0, 1, 0, p;\n\t}"
        : "=r"(done) : "r"(a), "r"(phase) : "memory");
    if (!done) {
        asm volatile(
            "{\n\t.reg .pred P1;\n\t"
            "WL_%=:\n\t"
            "mbarrier.try_wait.parity.acquire.cta.shared::cta.b64 P1, [%0], %1, 0x989680;\n\t"
            "@P1 bra.uni WD_%=;\n\t"
            "bra.uni WL_%=;\n\t"
            "WD_%=:\n\t}"
            :: "r"(a), "r"(phase) : "memory");
    }
}
// swizzled byte offset of (row 0..127, col 0..511 bf16) in a 128x512 tile
__device__ __forceinline__ uint32_t tile_off(int row, int col) {
    uint32_t byte = (uint32_t)(((row >> 3) + (col >> 6)*16)*1024
                               + (row & 7)*128 + (col & 63)*2);
    return byte ^ ((byte >> 3) & 0x70);
}
// same, within one staged 64-col block (col < 64)
__device__ __forceinline__ uint32_t blk_off(int row, int col) {
    uint32_t byte = (uint32_t)(((row >> 3) << 10) + ((row & 7) << 7) + (col << 1));
    return byte ^ ((byte >> 3) & 0x70);
}
__device__ __forceinline__ void split_bf16(float v, unsigned& h, unsigned& l) {
    __nv_bfloat16 hb = __float2bfloat16(v);
    float r = v - __bfloat162float(hb);
    __nv_bfloat16 lb = __float2bfloat16(r);
    h = (unsigned)__bfloat16_as_ushort(hb);
    l = (unsigned)__bfloat16_as_ushort(lb);
}
#define LDMATRIX_X4(r0, r1, r2, r3, addr) \
    asm volatile("ldmatrix.sync.aligned.m8n8.x4.shared.b16 {%0,%1,%2,%3}, [%4];" \
                 : "=r"(r0), "=r"(r1), "=r"(r2), "=r"(r3) : "r"(addr))
#define MMA_BF16(d, a, b) \
    asm volatile("mma.sync.aligned.m16n8k16.row.col.f32.bf16.bf16.f32 " \
                 "{%0,%1,%2,%3}, {%4,%5,%6,%7}, {%8,%9}, {%0,%1,%2,%3};" \
                 : "+f"((d)[0]), "+f"((d)[1]), "+f"((d)[2]), "+f"((d)[3]) \
                 : "r"((a)[0]), "r"((a)[1]), "r"((a)[2]), "r"((a)[3]), \
                   "r"((b)[0]), "r"((b)[1]))

// ---------------- prep: (B,T,K) -> [t][k][b], masked ----------------
__global__ void prep_kernel(const float* __restrict__ in, const int* __restrict__ len) {
    int idx = blockIdx.x * blockDim.x + threadIdx.x;
    if (idx >= TT*HH*BB) return;
    int b = idx & 63;
    int k = (idx >> 6) & 511;
    int t = idx >> 15;
    float v = 0.f;
    if (t < len[b]) v = in[((size_t)b*TT + t)*HH + k];
    g_xt[idx] = v;
}

// ---------------- pack W_hh[k][g*512+hid] -> wt[l][(hid*5+g)][k] ----------------
__global__ void packw_kernel(const float* __restrict__ weight) {
    int idx = blockIdx.x * blockDim.x + threadIdx.x;
    if (idx >= 4*HH*G5) return;
    int col = idx % G5;
    int k   = (idx / G5) % HH;
    int l   = idx / (G5*HH);
    int hid = col & 511, g = col >> 9;
    float v = weight[(size_t)l*LAYER_W_STRIDE + WHH_OFF + (size_t)k*G5 + col];
    g_wt[(size_t)l*(G5*HH) + (size_t)((hid*5 + g) << 9) + k] = v;
}

// ---------------- pack W_ih^T into swizzled split-bf16 B tiles [n][k] ---------
__global__ void packwb_kernel(const float* __restrict__ weight) {
    int idx = blockIdx.x * blockDim.x + threadIdx.x;
    if (idx >= 4*24*128*64) return;
    int cu  = idx & 63;
    int row = (idx >> 6) & 127;
    int nt  = (idx >> 13) % 24;
    int l   = (idx >> 13) / 24;
    int g = nt*128 + row;
    const float* wsrc = weight + (size_t)l*LAYER_W_STRIDE;
    unsigned h[8], lo[8];
    #pragma unroll
    for (int j = 0; j < 8; j++) {
        float v = wsrc[(size_t)(cu*8 + j)*G6 + g];
        split_bf16(v, h[j], lo[j]);
    }
    size_t off = (size_t)(l*24 + nt)*8192 + (tile_off(row, cu*8) >> 4);
    g_wbh[off] = make_uint4(h[0]|(h[1]<<16),  h[2]|(h[3]<<16),
                            h[4]|(h[5]<<16),  h[6]|(h[7]<<16));
    g_wbl[off] = make_uint4(lo[0]|(lo[1]<<16), lo[2]|(lo[3]<<16),
                            lo[4]|(lo[5]<<16), lo[6]|(lo[7]<<16));
}

// ------- convert layer input -> swizzled split-bf16 A tiles [m][k] -----------
// fuses (t,b)->m gather and odd-layer padded reversal
__global__ void conva_kernel(const float* __restrict__ xsrc,
                             const int* __restrict__ len, int rev) {
    int idx = blockIdx.x * blockDim.x + threadIdx.x;
    if (idx >= 128*128*64) return;
    int cu   = idx & 63;
    int row  = (idx >> 6) & 127;
    int tile = idx >> 13;
    int b = row & 63;
    int t = tile*2 + (row >> 6);
    if (rev) { int L = len[b]; if (t < L) t = L - 1 - t; }
    unsigned h[8], lo[8];
    #pragma unroll
    for (int j = 0; j < 8; j++) {
        float v = xsrc[((size_t)t*HH + cu*8 + j)*BB + b];
        split_bf16(v, h[j], lo[j]);
    }
    size_t off = (size_t)tile*8192 + (tile_off(row, cu*8) >> 4);
    g_xah[off] = make_uint4(h[0]|(h[1]<<16),  h[2]|(h[3]<<16),
                            h[4]|(h[5]<<16),  h[6]|(h[7]<<16));
    g_xal[off] = make_uint4(lo[0]|(lo[1]<<16), lo[2]|(lo[3]<<16),
                            lo[4]|(lo[5]<<16), lo[6]|(lo[7]<<16));
}

// ---------------- bf16-split mma.sync GEMM ----------------
// CTA: 128m x 128n x 512k; 8 warps (wm 0..3, wn 0..1) -> warp tile 32m x 64n.
// acc += Ah*Bh + Ah*Bl + Al*Bh. 2-stage cp.async.bulk pipeline (64k slices).
__global__ __launch_bounds__(256)
void gemm_mma_kernel(const uint8_t* __restrict__ Ah, const uint8_t* __restrict__ Al,
                     const uint8_t* __restrict__ Bh, const uint8_t* __restrict__ Bl,
                     float* __restrict__ XI)
{
    extern __shared__ __align__(1024) uint8_t smg[];
    int tid = threadIdx.x;
    int lane = tid & 31, wid = tid >> 5;
    int wm = wid & 3, wn = wid >> 2;
    int mt = blockIdx.x, nt = blockIdx.y;
    unsigned sm = smem_u32(smg);
    unsigned mbf = sm + 131072u;

    if (tid == 0) {
        mbar_init(mbf, 1); mbar_init(mbf + 8, 1);
        asm volatile("fence.proxy.async.shared::cta;" ::: "memory");
    }
    __syncthreads();

    const uint8_t* aH = Ah + (size_t)mt*131072;
    const uint8_t* aL = Al + (size_t)mt*131072;
    const uint8_t* bH = Bh + (size_t)nt*131072;
    const uint8_t* bL = Bl + (size_t)nt*131072;

    if (tid == 0) {
        #pragma unroll
        for (int s = 0; s < 2; s++) {
            unsigned sb = sm + (unsigned)s*65536u;
            mbar_expect_tx(mbf + 8*s, 65536u);
            bulk_g2s(sb,           aH + s*16384, 16384u, mbf + 8*s);
            bulk_g2s(sb + 16384u,  aL + s*16384, 16384u, mbf + 8*s);
            bulk_g2s(sb + 32768u,  bH + s*16384, 16384u, mbf + 8*s);
            bulk_g2s(sb + 49152u,  bL + s*16384, 16384u, mbf + 8*s);
        }
    }

    float acc[2][8][4];
    #pragma unroll
    for (int mi = 0; mi < 2; mi++)
        #pragma unroll
        for (int nj = 0; nj < 8; nj++)
            #pragma unroll
            for (int q = 0; q < 4; q++) acc[mi][nj][q] = 0.f;

    int r  = lane & 7;
    int ts = lane >> 3;
    // A ldmatrix lane geometry: row += 8*(ts&1), k += 8*(ts>>1)
    int arow0 = wm*32 + r + ((ts & 1) << 3);
    int akadd = (ts >> 1) << 3;
    // B ldmatrix lane geometry: row(n) += 8*(ts>>1), k += 8*(ts&1)
    int brow0 = wn*64 + r + ((ts >> 1) << 3);
    int bkadd = (ts & 1) << 3;

    for (int s = 0; s < 8; s++) {
        int p = s & 1;
        unsigned ph = (unsigned)((s >> 1) & 1);
        mbar_wait_parity(mbf + 8*p, ph);
        unsigned sb  = sm + (unsigned)p*65536u;
        unsigned sAh = sb, sAl = sb + 16384u;
        unsigned sBh = sb + 32768u, sBl = sb + 49152u;

        #pragma unroll
        for (int j = 0; j < 4; j++) {
            int kc = j*16 + akadd;
            uint32_t ah0[4], ah1[4], al0[4], al1[4];
            {
                unsigned o0 = blk_off(arow0,      kc);
                unsigned o1 = blk_off(arow0 + 16, kc);
                LDMATRIX_X4(ah0[0], ah0[1], ah0[2], ah0[3], sAh + o0);
                LDMATRIX_X4(ah1[0], ah1[1], ah1[2], ah1[3], sAh + o1);
                LDMATRIX_X4(al0[0], al0[1], al0[2], al0[3], sAl + o0);
                LDMATRIX_X4(al1[0], al1[1], al1[2], al1[3], sAl + o1);
            }
            int kb = j*16 + bkadd;
            uint32_t bh[8][2], bl[8][2];
            #pragma unroll
            for (int p4 = 0; p4 < 4; p4++) {
                unsigned ob = blk_off(brow0 + p4*16, kb);
                LDMATRIX_X4(bh[2*p4][0], bh[2*p4][1], bh[2*p4+1][0], bh[2*p4+1][1],
                            sBh + ob);
                LDMATRIX_X4(bl[2*p4][0], bl[2*p4][1], bl[2*p4+1][0], bl[2*p4+1][1],
                            sBl + ob);
            }
            #pragma unroll
            for (int nj = 0; nj < 8; nj++) {
                MMA_BF16(acc[0][nj], ah0, bh[nj]);
                MMA_BF16(acc[1][nj], ah1, bh[nj]);
                MMA_BF16(acc[0][nj], ah0, bl[nj]);
                MMA_BF16(acc[1][nj], ah1, bl[nj]);
                MMA_BF16(acc[0][nj], al0, bh[nj]);
                MMA_BF16(acc[1][nj], al1, bh[nj]);
            }
        }
        __syncthreads();        // all warps done reading stage p
        if (tid == 0 && s + 2 < 8) {
            int s2 = s + 2;
            mbar_expect_tx(mbf + 8*p, 65536u);
            bulk_g2s(sb,          aH + s2*16384, 16384u, mbf + 8*p);
            bulk_g2s(sb + 16384u, aL + s2*16384, 16384u, mbf + 8*p);
            bulk_g2s(sb + 32768u, bH + s2*16384, 16384u, mbf + 8*p);
            bulk_g2s(sb + 49152u, bL + s2*16384, 16384u, mbf + 8*p);
        }
    }

    // epilogue: regs -> xi[t][g][b]
    int g4 = lane >> 2, t4 = lane & 3;
    #pragma unroll
    for (int mi = 0; mi < 2; mi++) {
        #pragma unroll
        for (int half = 0; half < 2; half++) {
            int m = mt*128 + wm*32 + mi*16 + g4 + half*8;
            int t = m >> 6, b = m & 63;
            float* xo = XI + ((size_t)t*G6 + nt*128 + wn*64 + t4*2)*64 + b;
            #pragma unroll
            for (int nj = 0; nj < 8; nj++) {
                xo[(size_t)(nj*8)*64]       = acc[mi][nj][half*2];
                xo[(size_t)(nj*8 + 1)*64]   = acc[mi][nj][half*2 + 1];
            }
        }
    }
}

// ---------------- persistent per-layer recurrence (R10 verbatim) -------------
__global__ __launch_bounds__(288)
void lstm_layer_kernel(const float* __restrict__ xi_base,
                       const float* __restrict__ wt,
                       const float* __restrict__ bias,
                       const int*   __restrict__ len,
                       float* __restrict__ hbuf0,
                       float* __restrict__ hbuf1,
                       float* __restrict__ y,
                       int rev)
{
    extern __shared__ float smf[];
    int tid = threadIdx.x;
    int hid0 = blockIdx.x * 4;
    int grp  = blockIdx.x >> 5;

    unsigned smbase = smem_u32(smf);
    unsigned mbar0  = smbase + OFF_MBAR_BYTES;
    unsigned hdst0  = smbase + OFF_H * 4;

    int w8 = tid >> 5;
    int bp = tid & 31;
    int hl_o = tid >> 6;
    int b_o  = tid & 63;
    int hid_o = hid0 + (hl_o & 3);

    if (tid < 256) {
        const float4* ws = (const float4*)(wt + (size_t)hid0 * 5 * 512);
        float4* wd = (float4*)(smf + OFF_W);
        #pragma unroll
        for (int i = 0; i < 10; i++) wd[tid + i*256] = ws[tid + i*256];
    }
    if (tid == 256) {
        #pragma unroll
        for (int c = 0; c < 4; c++) mbar_init(mbar0 + 8*c, 1);
        asm volatile("fence.proxy.async.shared::cta;" ::: "memory");
    }

    float bval[5] = {0.f, 0.f, 0.f, 0.f, 0.f};
    int L = 0;
    float xiv[6] = {0.f, 0.f, 0.f, 0.f, 0.f, 0.f};
    if (tid < 256) {
        #pragma unroll
        for (int g = 0; g < 5; g++) bval[g] = bias[g*512 + hid_o];
        L = len[b_o];
        #pragma unroll
        for (int g = 0; g < 6; g++)
            xiv[g] = __ldcs(xi_base + (size_t)(g*512 + hid_o)*BB + b_o);
    }
    float c = 0.0f;

    const float* hin  = hbuf0;
    float*       hout = hbuf1;

    __syncthreads();

    if (tid == 256) {
        #pragma unroll
        for (int ch = 0; ch < 4; ch++) {
            mbar_expect_tx(mbar0 + 8*ch, 32768u);
            bulk_g2s(hdst0 + ch*32768u, hin + ch*8192, 32768u, mbar0 + 8*ch);
        }
    }

    for (int s = 0; s < TT; s++) {
        unsigned phase = (unsigned)(s & 1);

        if (tid < 256) {
            float2 acc[20];
            #pragma unroll
            for (int q = 0; q < 20; q++) acc[q] = make_float2(0.f, 0.f);

            #pragma unroll
            for (int ch = 0; ch < 4; ch++) {
                mbar_wait_parity(mbar0 + 8*ch, phase);
                const float* shh = smf + OFF_H + ch*8192 + 2*bp;
                const float* shw = smf + OFF_W + ch*128 + w8*16;
                #pragma unroll
                for (int k4 = 0; k4 < 16; k4 += 4) {
                    int kb = (w8*16 + k4) * 64;
                    float2 hv0 = *(const float2*)(shh + kb);
                    float2 hv1 = *(const float2*)(shh + kb + 64);
                    float2 hv2 = *(const float2*)(shh + kb + 128);
                    float2 hv3 = *(const float2*)(shh + kb + 192);
                    #pragma unroll
                    for (int q = 0; q < 20; q++) {
                        float4 w4 = *(const float4*)(shw + q*512 + k4);
                        acc[q] = ffma2(hv0, make_float2(w4.x, w4.x), acc[q]);
                        acc[q] = ffma2(hv1, make_float2(w4.y, w4.y), acc[q]);
                        acc[q] = ffma2(hv2, make_float2(w4.z, w4.z), acc[q]);
                        acc[q] = ffma2(hv3, make_float2(w4.w, w4.w), acc[q]);
                    }
                }
            }

            float* rb = smf + OFF_R + (w8*32 + bp)*42;
            #pragma unroll
            for (int q = 0; q < 20; q++) *(float2*)(rb + 2*q) = acc[q];
        }
        __syncthreads();                              // sync A

        float hn = 0.f;
        if (tid < 256) {
            float gv[5];
            #pragma unroll
            for (int g = 0; g < 5; g++) gv[g] = xiv[g] + bval[g];
            const float* rbase = smf + OFF_R + (b_o >> 1)*42 + (b_o & 1);
            #pragma unroll
            for (int w2 = 0; w2 < 8; w2++) {
                const float* p = rbase + w2*32*42;
                #pragma unroll
                for (int g = 0; g < 5; g++)
                    gv[g] += p[(hl_o*5 + g)*2];
            }

            float ig = sigmoidf_(gv[0]);
            float fg = sigmoidf_(gv[1]);
            float gc = tanhf(gv[2]);
            float og = sigmoidf_(gv[3]);
            float rg = sigmoidf_(gv[4]);
            float lin = xiv[5];

            float cn;
            if (s < L) {
                cn = fg*c + ig*gc;
                hn = rg*(og*tanhf(cn)) + (1.f - rg)*lin;
            } else {
                cn = 0.f; hn = 0.f;
            }
            c = cn;
            hout[hid_o*BB + b_o] = hn;
        }
        __syncthreads();                              // sync B

        int dst = rev ? ((s < L) ? (L - 1 - s) : s) : s;

        if (s != TT-1) {
            if (tid == 0)
                red_add_release_gpu(&g_cnt[grp], 1u);

            if (tid < 256) {
                y[((size_t)dst*HH + hid_o)*BB + b_o] = hn;
                const float* xs = xi_base + (size_t)(s+1)*G6*BB;
                #pragma unroll
                for (int g = 0; g < 6; g++)
                    xiv[g] = __ldcs(xs + (size_t)(g*512 + hid_o)*BB + b_o);
            }

            if (tid == 256) {
                const float* hsrc = hout;
                unsigned target = 32u * (unsigned)(s + 1);
                #pragma unroll
                for (int ch = 0; ch < 4; ch++) {
                    while (ld_acquire_gpu(&g_cnt[ch]) < target) __nanosleep(32);
                    mbar_expect_tx(mbar0 + 8*ch, 32768u);
                    bulk_g2s(hdst0 + ch*32768u, hsrc + ch*8192, 32768u, mbar0 + 8*ch);
                }
            }
        } else if (tid < 256) {
            y[((size_t)dst*HH + hid_o)*BB + b_o] = hn;
        }

        const float* tmp = hin; hin = hout; hout = (float*)tmp;
    }
}

// ---------------- final: [t][k][b] -> (B,T,K) ----------------
__global__ void out_kernel(const float* __restrict__ xt, float* __restrict__ out) {
    int idx = blockIdx.x * blockDim.x + threadIdx.x;
    if (idx >= TT*HH*BB) return;
    int k = idx & 511;
    int t = (idx >> 9) & 255;
    int b = idx >> 17;
    out[idx] = xt[((size_t)t*HH + k)*BB + b];
}

// ---------------- launch ----------------
extern "C" void kernel_launch(void* const* d_in, const int* in_sizes, int n_in,
                              void* d_out, int out_size)
{
    const float* inputs = nullptr;
    const float* weight = nullptr;
    const float* biasp  = nullptr;
    const int*   len    = nullptr;
    for (int i = 0; i < n_in; i++) {
        switch (in_sizes[i]) {
            case TT*BB*HH:  inputs = (const float*)d_in[i]; break;  // 8388608
            case 11534336:  weight = (const float*)d_in[i]; break;
            case 4*G5:      biasp  = (const float*)d_in[i]; break;  // 10240
            case BB:        len    = (const int*)  d_in[i]; break;  // 64
        }
    }

    float *pxt, *pyt, *pxi, *ph0, *ph1, *pwt;
    unsigned* pcnt;
    uint4 *pwbh, *pwbl, *pxah, *pxal;
    cudaGetSymbolAddress((void**)&pxt,  g_xt);
    cudaGetSymbolAddress((void**)&pyt,  g_yt);
    cudaGetSymbolAddress((void**)&pxi,  g_xi);
    cudaGetSymbolAddress((void**)&ph0,  g_h0);
    cudaGetSymbolAddress((void**)&ph1,  g_h1);
    cudaGetSymbolAddress((void**)&pwt,  g_wt);
    cudaGetSymbolAddress((void**)&pcnt, g_cnt);
    cudaGetSymbolAddress((void**)&pwbh, g_wbh);
    cudaGetSymbolAddress((void**)&pwbl, g_wbl);
    cudaGetSymbolAddress((void**)&pxah, g_xah);
    cudaGetSymbolAddress((void**)&pxal, g_xal);

    cudaFuncSetAttribute(lstm_layer_kernel,
                         cudaFuncAttributeMaxDynamicSharedMemorySize, SMEM_LSTM);
    cudaFuncSetAttribute(gemm_mma_kernel,
                         cudaFuncAttributeMaxDynamicSharedMemorySize, SMEM_GMM);

    prep_kernel<<<(TT*HH*BB + 255)/256, 256>>>(inputs, len);
    packw_kernel<<<(4*HH*G5 + 255)/256, 256>>>(weight);
    packwb_kernel<<<(4*24*128*64)/256, 256>>>(weight);

    float* xin  = pxt;
    float* yout = pyt;
    for (int l = 0; l < 4; l++) {
        int rev = l & 1;
        conva_kernel<<<(128*128*64)/256, 256>>>(xin, len, rev);
        gemm_mma_kernel<<<dim3(128, 24), 256, SMEM_GMM>>>(
            (const uint8_t*)pxah, (const uint8_t*)pxal,
            (const uint8_t*)(pwbh + (size_t)l*24*8192),
            (const uint8_t*)(pwbl + (size_t)l*24*8192),
            pxi);
        cudaMemsetAsync(ph0, 0, (size_t)HH*BB*sizeof(float));
        cudaMemsetAsync(pcnt, 0, 4*sizeof(unsigned));
        lstm_layer_kernel<<<NCTA, 288, SMEM_LSTM>>>(
            pxi, pwt + (size_t)l*G5*HH, biasp + (size_t)l*G5,
            len, ph0, ph1, yout, rev);
        float* tmp = xin; xin = yout; yout = tmp;
    }
    out_kernel<<<(TT*HH*BB + 255)/256, 256>>>(xin, (float*)d_out);
}

// round 14
// speedup vs baseline: 1.6082x; 1.1558x over previous
#include <cuda_runtime.h>
#include <cuda_bf16.h>
#include <cstdint>
#include <cstddef>

#define TT 256
#define BB 64
#define HH 512
#define G6 3072
#define G5 2560
#define LAYER_W_STRIDE (512*3072 + 512*2560)   /* 2883584 */
#define WHH_OFF (512*3072)                      /* 1572864 */
#define NCTA 128

// lstm smem (floats): weights 64KB | h planes 128KB | D buf 8.5KB | mbars
#define OWQ_F 0
#define OH_F  16384
#define OD_F  49152
#define OFF_MBAR_B ((49152 + 2176) * 4)   /* 205312 */
#define SMEM_LSTM (OFF_MBAR_B + 64)

// gemm smem: 2 stages x (Ah|Al|Bh|Bl) x 16KB = 131072 B + mbars
#define SMEM_GMM (131072 + 64)

// ---------------- device scratch ----------------
__device__ float g_xt[(size_t)TT*HH*BB];          // layer input  [t][k][b]
__device__ float g_yt[(size_t)TT*HH*BB];          // layer output [t][k][b]
__device__ float g_xi[(size_t)TT*G6*BB];          // xi [t][g][b]
__device__ unsigned char g_hb0[4*32768];          // h split planes, dbuf A
__device__ unsigned char g_hb1[4*32768];          // h split planes, dbuf B
__device__ unsigned char g_whq[(size_t)4*128*65536]; // W_hh swizzled bf16 [l][grp][hi|lo]
__device__ unsigned g_cnt[4];                     // per-group monotonic counters
// xi-GEMM operand tiles (pre-swizzled SW128 blocked-atom, bf16 split)
__device__ uint4 g_wbh[(size_t)4*24*8192];
__device__ uint4 g_wbl[(size_t)4*24*8192];
__device__ uint4 g_xah[(size_t)128*8192];
__device__ uint4 g_xal[(size_t)128*8192];

// ---------------- helpers ----------------
__device__ __forceinline__ float2 ffma2(float2 a, float2 b, float2 c) {
    union U { float2 f; unsigned long long u; };
    U A, B, C, D;
    A.f = a; B.f = b; C.f = c;
    asm("fma.rn.f32x2 %0, %1, %2, %3;" : "=l"(D.u) : "l"(A.u), "l"(B.u), "l"(C.u));
    return D.f;
}
__device__ __forceinline__ float sigmoidf_(float x) {
    return 1.0f / (1.0f + __expf(-x));
}
__device__ __forceinline__ void red_add_release_gpu(unsigned* p, unsigned v) {
    asm volatile("red.release.gpu.add.u32 [%0], %1;" :: "l"(p), "r"(v) : "memory");
}
__device__ __forceinline__ unsigned ld_acquire_gpu(const unsigned* p) {
    unsigned v;
    asm volatile("ld.acquire.gpu.u32 %0, [%1];" : "=r"(v) : "l"(p) : "memory");
    return v;
}
__device__ __forceinline__ unsigned smem_u32(const void* p) {
    unsigned a;
    asm("{ .reg .u64 t; cvta.to.shared.u64 t, %1; cvt.u32.u64 %0, t; }"
        : "=r"(a) : "l"(p));
    return a;
}
__device__ __forceinline__ void mbar_init(unsigned a, unsigned cnt) {
    asm volatile("mbarrier.init.shared.b64 [%0], %1;" :: "r"(a), "r"(cnt) : "memory");
}
__device__ __forceinline__ void mbar_expect_tx(unsigned a, unsigned bytes) {
    asm volatile("mbarrier.arrive.expect_tx.shared.b64 _, [%0], %1;"
                 :: "r"(a), "r"(bytes) : "memory");
}
__device__ __forceinline__ void bulk_g2s(unsigned dst, const void* src,
                                         unsigned bytes, unsigned mbar) {
    asm volatile("cp.async.bulk.shared::cluster.global.mbarrier::complete_tx::bytes "
                 "[%0], [%1], %2, [%3];"
                 :: "r"(dst), "l"(src), "r"(bytes), "r"(mbar) : "memory");
}
__device__ __forceinline__ void mbar_wait_parity(unsigned a, unsigned phase) {
    unsigned done;
    asm volatile(
        "{\n\t.reg .pred p;\n\t"
        "mbarrier.try_wait.parity.acquire.cta.shared::cta.b64 p, [%1], %2;\n\t"
        "selp.b32 %0, 1, 0, p;\n\t}"
        : "=r"(done) : "r"(a), "r"(phase) : "memory");
    if (!done) {
        asm volatile(
            "{\n\t.reg .pred P1;\n\t"
            "WL_%=:\n\t"
            "mbarrier.try_wait.parity.acquire.cta.shared::cta.b64 P1, [%0], %1, 0x989680;\n\t"
            "@P1 bra.uni WD_%=;\n\t"
            "bra.uni WL_%=;\n\t"
            "WD_%=:\n\t}"
            :: "r"(a), "r"(phase) : "memory");
    }
}
// swizzled byte offset of (row 0..127, col 0..511 bf16) in a 128x512 tile
__device__ __forceinline__ uint32_t tile_off(int row, int col) {
    uint32_t byte = (uint32_t)(((row >> 3) + (col >> 6)*16)*1024
                               + (row & 7)*128 + (col & 63)*2);
    return byte ^ ((byte >> 3) & 0x70);
}
// within one staged 64-col block (col < 64), 128 rows
__device__ __forceinline__ uint32_t blk_off(int row, int col) {
    uint32_t byte = (uint32_t)(((row >> 3) << 10) + ((row & 7) << 7) + (col << 1));
    return byte ^ ((byte >> 3) & 0x70);
}
// 64-row x 128-col h plane chunk (16KB)
__device__ __forceinline__ uint32_t hplane_off(int row, int kl) {
    uint32_t byte = (uint32_t)((((row >> 3) + ((kl >> 6) << 3)) << 10)
                               + ((row & 7) << 7) + ((kl & 63) << 1));
    return byte ^ ((byte >> 3) & 0x70);
}
// 32-row x 512-col weight plane (32KB)
__device__ __forceinline__ uint32_t wplane_off(int row, int col) {
    uint32_t byte = (uint32_t)((((row >> 3) + ((col >> 6) << 2)) << 10)
                               + ((row & 7) << 7) + ((col & 63) << 1));
    return byte ^ ((byte >> 3) & 0x70);
}
__device__ __forceinline__ void split_bf16(float v, unsigned& h, unsigned& l) {
    __nv_bfloat16 hb = __float2bfloat16(v);
    float r = v - __bfloat162float(hb);
    __nv_bfloat16 lb = __float2bfloat16(r);
    h = (unsigned)__bfloat16_as_ushort(hb);
    l = (unsigned)__bfloat16_as_ushort(lb);
}
#define LDMATRIX_X4(r0, r1, r2, r3, addr) \
    asm volatile("ldmatrix.sync.aligned.m8n8.x4.shared.b16 {%0,%1,%2,%3}, [%4];" \
                 : "=r"(r0), "=r"(r1), "=r"(r2), "=r"(r3) : "r"(addr))
#define MMA_BF16(d, a, b) \
    asm volatile("mma.sync.aligned.m16n8k16.row.col.f32.bf16.bf16.f32 " \
                 "{%0,%1,%2,%3}, {%4,%5,%6,%7}, {%8,%9}, {%0,%1,%2,%3};" \
                 : "+f"((d)[0]), "+f"((d)[1]), "+f"((d)[2]), "+f"((d)[3]) \
                 : "r"((a)[0]), "r"((a)[1]), "r"((a)[2]), "r"((a)[3]), \
                   "r"((b)[0]), "r"((b)[1]))

// ---------------- prep: (B,T,K) -> [t][k][b], masked ----------------
__global__ void prep_kernel(const float* __restrict__ in, const int* __restrict__ len) {
    int idx = blockIdx.x * blockDim.x + threadIdx.x;
    if (idx >= TT*HH*BB) return;
    int b = idx & 63;
    int k = (idx >> 6) & 511;
    int t = idx >> 15;
    float v = 0.f;
    if (t < len[b]) v = in[((size_t)b*TT + t)*HH + k];
    g_xt[idx] = v;
}

// ------- pack W_hh into per-CTA swizzled split-bf16 B tiles [q32][k512] -------
__global__ void packwq_kernel(const float* __restrict__ weight) {
    int idx = blockIdx.x * blockDim.x + threadIdx.x;
    if (idx >= 4*128*32*64) return;
    int cu  = idx & 63;            // k chunk of 8
    int row = (idx >> 6) & 31;     // q row
    int gq  = (idx >> 11) & 127;   // hid group (CTA)
    int l   = idx >> 18;
    unsigned h[8], lo[8];
    if (row < 20) {
        int hid = gq*4 + row/5;
        int g   = row % 5;
        const float* wsrc = weight + (size_t)l*LAYER_W_STRIDE + WHH_OFF;
        #pragma unroll
        for (int j = 0; j < 8; j++) {
            float v = wsrc[(size_t)(cu*8 + j)*G5 + g*512 + hid];
            split_bf16(v, h[j], lo[j]);
        }
    } else {
        #pragma unroll
        for (int j = 0; j < 8; j++) { h[j] = 0; lo[j] = 0; }
    }
    uint32_t off = wplane_off(row, cu*8);
    unsigned char* dst = g_whq + (size_t)(l*128 + gq)*65536;
    *(uint4*)(dst + off)         = make_uint4(h[0]|(h[1]<<16),  h[2]|(h[3]<<16),
                                              h[4]|(h[5]<<16),  h[6]|(h[7]<<16));
    *(uint4*)(dst + 32768 + off) = make_uint4(lo[0]|(lo[1]<<16), lo[2]|(lo[3]<<16),
                                              lo[4]|(lo[5]<<16), lo[6]|(lo[7]<<16));
}

// ---------------- pack W_ih^T into swizzled split-bf16 B tiles [n][k] ---------
__global__ void packwb_kernel(const float* __restrict__ weight) {
    int idx = blockIdx.x * blockDim.x + threadIdx.x;
    if (idx >= 4*24*128*64) return;
    int cu  = idx & 63;
    int row = (idx >> 6) & 127;
    int nt  = (idx >> 13) % 24;
    int l   = (idx >> 13) / 24;
    int g = nt*128 + row;
    const float* wsrc = weight + (size_t)l*LAYER_W_STRIDE;
    unsigned h[8], lo[8];
    #pragma unroll
    for (int j = 0; j < 8; j++) {
        float v = wsrc[(size_t)(cu*8 + j)*G6 + g];
        split_bf16(v, h[j], lo[j]);
    }
    size_t off = (size_t)(l*24 + nt)*8192 + (tile_off(row, cu*8) >> 4);
    g_wbh[off] = make_uint4(h[0]|(h[1]<<16),  h[2]|(h[3]<<16),
                            h[4]|(h[5]<<16),  h[6]|(h[7]<<16));
    g_wbl[off] = make_uint4(lo[0]|(lo[1]<<16), lo[2]|(lo[3]<<16),
                            lo[4]|(lo[5]<<16), lo[6]|(lo[7]<<16));
}

// ------- convert layer input -> swizzled split-bf16 A tiles [m][k] -----------
__global__ void conva_kernel(const float* __restrict__ xsrc,
                             const int* __restrict__ len, int rev) {
    int idx = blockIdx.x * blockDim.x + threadIdx.x;
    if (idx >= 128*128*64) return;
    int cu   = idx & 63;
    int row  = (idx >> 6) & 127;
    int tile = idx >> 13;
    int b = row & 63;
    int t = tile*2 + (row >> 6);
    if (rev) { int L = len[b]; if (t < L) t = L - 1 - t; }
    unsigned h[8], lo[8];
    #pragma unroll
    for (int j = 0; j < 8; j++) {
        float v = xsrc[((size_t)t*HH + cu*8 + j)*BB + b];
        split_bf16(v, h[j], lo[j]);
    }
    size_t off = (size_t)tile*8192 + (tile_off(row, cu*8) >> 4);
    g_xah[off] = make_uint4(h[0]|(h[1]<<16),  h[2]|(h[3]<<16),
                            h[4]|(h[5]<<16),  h[6]|(h[7]<<16));
    g_xal[off] = make_uint4(lo[0]|(lo[1]<<16), lo[2]|(lo[3]<<16),
                            lo[4]|(lo[5]<<16), lo[6]|(lo[7]<<16));
}

// ---------------- bf16-split mma.sync xi GEMM (R13 passing version) ----------
__global__ __launch_bounds__(256)
void gemm_mma_kernel(const uint8_t* __restrict__ Ah, const uint8_t* __restrict__ Al,
                     const uint8_t* __restrict__ Bh, const uint8_t* __restrict__ Bl,
                     float* __restrict__ XI)
{
    extern __shared__ __align__(1024) uint8_t smg[];
    int tid = threadIdx.x;
    int lane = tid & 31, wid = tid >> 5;
    int wm = wid & 3, wn = wid >> 2;
    int mt = blockIdx.x, nt = blockIdx.y;
    unsigned sm = smem_u32(smg);
    unsigned mbf = sm + 131072u;

    if (tid == 0) {
        mbar_init(mbf, 1); mbar_init(mbf + 8, 1);
        asm volatile("fence.proxy.async.shared::cta;" ::: "memory");
    }
    __syncthreads();

    const uint8_t* aH = Ah + (size_t)mt*131072;
    const uint8_t* aL = Al + (size_t)mt*131072;
    const uint8_t* bH = Bh + (size_t)nt*131072;
    const uint8_t* bL = Bl + (size_t)nt*131072;

    if (tid == 0) {
        #pragma unroll
        for (int s = 0; s < 2; s++) {
            unsigned sb = sm + (unsigned)s*65536u;
            mbar_expect_tx(mbf + 8*s, 65536u);
            bulk_g2s(sb,           aH + s*16384, 16384u, mbf + 8*s);
            bulk_g2s(sb + 16384u,  aL + s*16384, 16384u, mbf + 8*s);
            bulk_g2s(sb + 32768u,  bH + s*16384, 16384u, mbf + 8*s);
            bulk_g2s(sb + 49152u,  bL + s*16384, 16384u, mbf + 8*s);
        }
    }

    float acc[2][8][4];
    #pragma unroll
    for (int mi = 0; mi < 2; mi++)
        #pragma unroll
        for (int nj = 0; nj < 8; nj++)
            #pragma unroll
            for (int q = 0; q < 4; q++) acc[mi][nj][q] = 0.f;

    int r  = lane & 7;
    int ts = lane >> 3;
    int arow0 = wm*32 + r + ((ts & 1) << 3);
    int akadd = (ts >> 1) << 3;
    int brow0 = wn*64 + r + ((ts >> 1) << 3);
    int bkadd = (ts & 1) << 3;

    for (int s = 0; s < 8; s++) {
        int p = s & 1;
        unsigned ph = (unsigned)((s >> 1) & 1);
        mbar_wait_parity(mbf + 8*p, ph);
        unsigned sb  = sm + (unsigned)p*65536u;
        unsigned sAh = sb, sAl = sb + 16384u;
        unsigned sBh = sb + 32768u, sBl = sb + 49152u;

        #pragma unroll
        for (int j = 0; j < 4; j++) {
            int kc = j*16 + akadd;
            uint32_t ah0[4], ah1[4], al0[4], al1[4];
            {
                unsigned o0 = blk_off(arow0,      kc);
                unsigned o1 = blk_off(arow0 + 16, kc);
                LDMATRIX_X4(ah0[0], ah0[1], ah0[2], ah0[3], sAh + o0);
                LDMATRIX_X4(ah1[0], ah1[1], ah1[2], ah1[3], sAh + o1);
                LDMATRIX_X4(al0[0], al0[1], al0[2], al0[3], sAl + o0);
                LDMATRIX_X4(al1[0], al1[1], al1[2], al1[3], sAl + o1);
            }
            int kb = j*16 + bkadd;
            uint32_t bh[8][2], bl[8][2];
            #pragma unroll
            for (int p4 = 0; p4 < 4; p4++) {
                unsigned ob = blk_off(brow0 + p4*16, kb);
                LDMATRIX_X4(bh[2*p4][0], bh[2*p4][1], bh[2*p4+1][0], bh[2*p4+1][1],
                            sBh + ob);
                LDMATRIX_X4(bl[2*p4][0], bl[2*p4][1], bl[2*p4+1][0], bl[2*p4+1][1],
                            sBl + ob);
            }
            #pragma unroll
            for (int nj = 0; nj < 8; nj++) {
                MMA_BF16(acc[0][nj], ah0, bh[nj]);
                MMA_BF16(acc[1][nj], ah1, bh[nj]);
                MMA_BF16(acc[0][nj], ah0, bl[nj]);
                MMA_BF16(acc[1][nj], ah1, bl[nj]);
                MMA_BF16(acc[0][nj], al0, bh[nj]);
                MMA_BF16(acc[1][nj], al1, bh[nj]);
            }
        }
        __syncthreads();
        if (tid == 0 && s + 2 < 8) {
            int s2 = s + 2;
            mbar_expect_tx(mbf + 8*p, 65536u);
            bulk_g2s(sb,          aH + s2*16384, 16384u, mbf + 8*p);
            bulk_g2s(sb + 16384u, aL + s2*16384, 16384u, mbf + 8*p);
            bulk_g2s(sb + 32768u, bH + s2*16384, 16384u, mbf + 8*p);
            bulk_g2s(sb + 49152u, bL + s2*16384, 16384u, mbf + 8*p);
        }
    }

    int g4 = lane >> 2, t4 = lane & 3;
    #pragma unroll
    for (int mi = 0; mi < 2; mi++) {
        #pragma unroll
        for (int half = 0; half < 2; half++) {
            int m = mt*128 + wm*32 + mi*16 + g4 + half*8;
            int t = m >> 6, b = m & 63;
            float* xo = XI + ((size_t)t*G6 + nt*128 + wn*64 + t4*2)*64 + b;
            #pragma unroll
            for (int nj = 0; nj < 8; nj++) {
                xo[(size_t)(nj*8)*64]       = acc[mi][nj][half*2];
                xo[(size_t)(nj*8 + 1)*64]   = acc[mi][nj][half*2 + 1];
            }
        }
    }
}

// ---------------- persistent per-layer recurrence (tensor-core math) ---------
// R10 skeleton: same chunks, mbarriers, per-group counters, staging warp.
// Math phase: warp (wm 0..3, wn 0..1) computes D[m16(b) x n16(q)] over K=512
// via mma.sync bf16 split (Ah*Bh + Ah*Bl + Al*Bh). h stored globally as
// pre-swizzled bf16 hi/lo planes so TMA-staged smem is ldmatrix-ready.
__global__ __launch_bounds__(288)
void lstm_layer_kernel(const float* __restrict__ xi_base,
                       const unsigned char* __restrict__ wq,   // [grp][hi32KB|lo32KB]
                       const float* __restrict__ bias,
                       const int*   __restrict__ len,
                       unsigned char* __restrict__ hbuf0,
                       unsigned char* __restrict__ hbuf1,
                       float* __restrict__ y,
                       int rev)
{
    extern __shared__ float smf[];
    int tid = threadIdx.x;
    int hid0 = blockIdx.x * 4;
    int grp  = blockIdx.x >> 5;

    unsigned smbase = smem_u32(smf);
    unsigned smW    = smbase + OWQ_F*4;     // weights: hi 32KB | lo 32KB
    unsigned smH    = smbase + OH_F*4;      // h planes: 4 chunks x (hi16|lo16)
    unsigned mbar0  = smbase + OFF_MBAR_B;

    int lane = tid & 31, wid = tid >> 5;
    int wm = wid & 3, wn = (wid >> 2) & 1;  // valid for wid<8
    // output-phase mapping
    int hl_o = (tid >> 6) & 3;
    int b_o  = tid & 63;
    int hid_o = hid0 + hl_o;

    // one-time: weights -> smem (64KB linear; pre-swizzled in global)
    if (tid < 256) {
        const uint4* ws = (const uint4*)(wq + (size_t)blockIdx.x*65536);
        uint4* wd = (uint4*)smf;
        #pragma unroll
        for (int i = 0; i < 16; i++) wd[tid + i*256] = ws[tid + i*256];
    }
    if (tid == 256) {
        #pragma unroll
        for (int c = 0; c < 4; c++) mbar_init(mbar0 + 8*c, 1);
        asm volatile("fence.proxy.async.shared::cta;" ::: "memory");
    }

    float bval[5] = {0.f, 0.f, 0.f, 0.f, 0.f};
    int L = 0;
    float xiv[6] = {0.f, 0.f, 0.f, 0.f, 0.f, 0.f};
    if (tid < 256) {
        #pragma unroll
        for (int g = 0; g < 5; g++) bval[g] = bias[g*512 + hid_o];
        L = len[b_o];
        #pragma unroll
        for (int g = 0; g < 6; g++)
            xiv[g] = __ldcs(xi_base + (size_t)(g*512 + hid_o)*BB + b_o);
    }
    float c = 0.0f;

    unsigned char* hin  = hbuf0;
    unsigned char* hout = hbuf1;

    // ldmatrix lane geometry (R13-verified)
    int r  = lane & 7;
    int ts = lane >> 3;
    int arow = wm*16 + r + ((ts & 1) << 3);      // b row 0..63
    int ak   = (ts >> 1) << 3;
    int brow = wn*16 + r + ((ts >> 1) << 3);     // q row 0..31
    int bk   = (ts & 1) << 3;

    __syncthreads();

    if (tid == 256) {
        #pragma unroll
        for (int ch = 0; ch < 4; ch++) {
            mbar_expect_tx(mbar0 + 8*ch, 32768u);
            bulk_g2s(smH + ch*32768u, hin + ch*32768, 32768u, mbar0 + 8*ch);
        }
    }

    for (int s = 0; s < TT; s++) {
        unsigned phase = (unsigned)(s & 1);

        if (tid < 256) {
            float acc[2][4];
            #pragma unroll
            for (int nj = 0; nj < 2; nj++)
                #pragma unroll
                for (int q = 0; q < 4; q++) acc[nj][q] = 0.f;

            #pragma unroll
            for (int ch = 0; ch < 4; ch++) {
                mbar_wait_parity(mbar0 + 8*ch, phase);
                unsigned sAh = smH + ch*32768u;
                unsigned sAl = sAh + 16384u;
                #pragma unroll
                for (int j = 0; j < 8; j++) {         // k16 tiles in chunk
                    unsigned ao = hplane_off(arow, j*16 + ak);
                    uint32_t ah[4], al[4];
                    LDMATRIX_X4(ah[0], ah[1], ah[2], ah[3], sAh + ao);
                    LDMATRIX_X4(al[0], al[1], al[2], al[3], sAl + ao);
                    int kg = ch*128 + j*16 + bk;
                    unsigned bo = wplane_off(brow, kg);
                    uint32_t bh[2][2], bl[2][2];
                    LDMATRIX_X4(bh[0][0], bh[0][1], bh[1][0], bh[1][1], smW + bo);
                    LDMATRIX_X4(bl[0][0], bl[0][1], bl[1][0], bl[1][1],
                                smW + 32768u + bo);
                    #pragma unroll
                    for (int nj = 0; nj < 2; nj++) {
                        MMA_BF16(acc[nj], ah, bh[nj]);
                        MMA_BF16(acc[nj], ah, bl[nj]);
                        MMA_BF16(acc[nj], al, bh[nj]);
                    }
                }
            }

            // D frags -> smem Dbuf[b][q] (pitch 34)
            float* db = smf + OD_F;
            int drow = wm*16 + (lane >> 2);
            int dcol = wn*16 + (lane & 3)*2;
            #pragma unroll
            for (int nj = 0; nj < 2; nj++) {
                db[drow*34 + dcol + nj*8]       = acc[nj][0];
                db[drow*34 + dcol + nj*8 + 1]   = acc[nj][1];
                db[(drow+8)*34 + dcol + nj*8]   = acc[nj][2];
                db[(drow+8)*34 + dcol + nj*8+1] = acc[nj][3];
            }
        }
        __syncthreads();                              // sync A

        float hn = 0.f;
        if (tid < 256) {
            const float* db = smf + OD_F + b_o*34 + hl_o*5;
            float gv[5];
            #pragma unroll
            for (int g = 0; g < 5; g++) gv[g] = xiv[g] + bval[g] + db[g];

            float ig = sigmoidf_(gv[0]);
            float fg = sigmoidf_(gv[1]);
            float gc = tanhf(gv[2]);
            float og = sigmoidf_(gv[3]);
            float rg = sigmoidf_(gv[4]);
            float lin = xiv[5];

            float cn;
            if (s < L) {
                cn = fg*c + ig*gc;
                hn = rg*(og*tanhf(cn)) + (1.f - rg)*lin;
            } else {
                cn = 0.f; hn = 0.f;
            }
            c = cn;
            // store h as split bf16 into pre-swizzled global planes
            unsigned hi16, lo16;
            split_bf16(hn, hi16, lo16);
            int chn = hid_o >> 7, kl = hid_o & 127;
            uint32_t loc = hplane_off(b_o, kl);
            *(uint16_t*)(hout + chn*32768 + loc)          = (uint16_t)hi16;
            *(uint16_t*)(hout + chn*32768 + 16384 + loc)  = (uint16_t)lo16;
        }
        __syncthreads();                              // sync B

        int dst = rev ? ((s < L) ? (L - 1 - s) : s) : s;

        if (s != TT-1) {
            if (tid == 0)
                red_add_release_gpu(&g_cnt[grp], 1u);

            if (tid < 256) {
                y[((size_t)dst*HH + hid_o)*BB + b_o] = hn;
                const float* xs = xi_base + (size_t)(s+1)*G6*BB;
                #pragma unroll
                for (int g = 0; g < 6; g++)
                    xiv[g] = __ldcs(xs + (size_t)(g*512 + hid_o)*BB + b_o);
            }

            if (tid == 256) {
                const unsigned char* hsrc = hout;
                unsigned target = 32u * (unsigned)(s + 1);
                #pragma unroll
                for (int ch = 0; ch < 4; ch++) {
                    while (ld_acquire_gpu(&g_cnt[ch]) < target) __nanosleep(32);
                    mbar_expect_tx(mbar0 + 8*ch, 32768u);
                    bulk_g2s(smH + ch*32768u, hsrc + ch*32768, 32768u, mbar0 + 8*ch);
                }
            }
        } else if (tid < 256) {
            y[((size_t)dst*HH + hid_o)*BB + b_o] = hn;
        }

        unsigned char* tmp = hin; hin = hout; hout = tmp;
    }
}

// ---------------- final: [t][k][b] -> (B,T,K) ----------------
__global__ void out_kernel(const float* __restrict__ xt, float* __restrict__ out) {
    int idx = blockIdx.x * blockDim.x + threadIdx.x;
    if (idx >= TT*HH*BB) return;
    int k = idx & 511;
    int t = (idx >> 9) & 255;
    int b = idx >> 17;
    out[idx] = xt[((size_t)t*HH + k)*BB + b];
}

// ---------------- launch ----------------
extern "C" void kernel_launch(void* const* d_in, const int* in_sizes, int n_in,
                              void* d_out, int out_size)
{
    const float* inputs = nullptr;
    const float* weight = nullptr;
    const float* biasp  = nullptr;
    const int*   len    = nullptr;
    for (int i = 0; i < n_in; i++) {
        switch (in_sizes[i]) {
            case TT*BB*HH:  inputs = (const float*)d_in[i]; break;  // 8388608
            case 11534336:  weight = (const float*)d_in[i]; break;
            case 4*G5:      biasp  = (const float*)d_in[i]; break;  // 10240
            case BB:        len    = (const int*)  d_in[i]; break;  // 64
        }
    }

    float *pxt, *pyt, *pxi;
    unsigned char *phb0, *phb1, *pwhq;
    unsigned* pcnt;
    uint4 *pwbh, *pwbl, *pxah, *pxal;
    cudaGetSymbolAddress((void**)&pxt,  g_xt);
    cudaGetSymbolAddress((void**)&pyt,  g_yt);
    cudaGetSymbolAddress((void**)&pxi,  g_xi);
    cudaGetSymbolAddress((void**)&phb0, g_hb0);
    cudaGetSymbolAddress((void**)&phb1, g_hb1);
    cudaGetSymbolAddress((void**)&pwhq, g_whq);
    cudaGetSymbolAddress((void**)&pcnt, g_cnt);
    cudaGetSymbolAddress((void**)&pwbh, g_wbh);
    cudaGetSymbolAddress((void**)&pwbl, g_wbl);
    cudaGetSymbolAddress((void**)&pxah, g_xah);
    cudaGetSymbolAddress((void**)&pxal, g_xal);

    cudaFuncSetAttribute(lstm_layer_kernel,
                         cudaFuncAttributeMaxDynamicSharedMemorySize, SMEM_LSTM);
    cudaFuncSetAttribute(gemm_mma_kernel,
                         cudaFuncAttributeMaxDynamicSharedMemorySize, SMEM_GMM);

    prep_kernel<<<(TT*HH*BB + 255)/256, 256>>>(inputs, len);
    packwq_kernel<<<(4*128*32*64)/256, 256>>>(weight);
    packwb_kernel<<<(4*24*128*64)/256, 256>>>(weight);

    float* xin  = pxt;
    float* yout = pyt;
    for (int l = 0; l < 4; l++) {
        int rev = l & 1;
        conva_kernel<<<(128*128*64)/256, 256>>>(xin, len, rev);
        gemm_mma_kernel<<<dim3(128, 24), 256, SMEM_GMM>>>(
            (const uint8_t*)pxah, (const uint8_t*)pxal,
            (const uint8_t*)(pwbh + (size_t)l*24*8192),
            (const uint8_t*)(pwbl + (size_t)l*24*8192),
            pxi);
        cudaMemsetAsync(phb0, 0, 4*32768);
        cudaMemsetAsync(pcnt, 0, 4*sizeof(unsigned));
        lstm_layer_kernel<<<NCTA, 288, SMEM_LSTM>>>(
            pxi, pwhq + (size_t)l*128*65536, biasp + (size_t)l*G5,
            len, phb0, phb1, yout, rev);
        float* tmp = xin; xin = yout; yout = tmp;
    }
    out_kernel<<<(TT*HH*BB + 255)/256, 256>>>(xin, (float*)d_out);
}

// round 15
// speedup vs baseline: 1.6240x; 1.0098x over previous
#include <cuda_runtime.h>
#include <cuda_bf16.h>
#include <cstdint>
#include <cstddef>

#define TT 256
#define BB 64
#define HH 512
#define G6 3072
#define G5 2560
#define LAYER_W_STRIDE (512*3072 + 512*2560)   /* 2883584 */
#define WHH_OFF (512*3072)                      /* 1572864 */
#define NCTA 128

// lstm smem (floats): weights 64KB | h planes 128KB | D buf 8.5KB | mbars
#define OWQ_F 0
#define OH_F  16384
#define OD_F  49152
#define OFF_MBAR_B ((49152 + 2176) * 4)   /* 205312 */
#define SMEM_LSTM (OFF_MBAR_B + 64)       /* 8 mbarriers */

// gemm smem: 3 stages x (Ah|Al|Bh|Bl) x 16KB = 196608 B + mbars
#define SMEM_GMM (196608 + 64)

// ---------------- device scratch ----------------
__device__ float g_xt[(size_t)TT*HH*BB];          // layer input  [t][k][b]
__device__ float g_yt[(size_t)TT*HH*BB];          // layer output [t][k][b]
__device__ float g_xi[(size_t)TT*G6*BB];          // xi [t][g][b]
__device__ unsigned char g_hb0[4*32768];          // h split planes, dbuf A
__device__ unsigned char g_hb1[4*32768];          // h split planes, dbuf B
__device__ unsigned char g_whq[(size_t)4*128*65536]; // W_hh swizzled bf16 [l][grp][hi|lo]
__device__ unsigned g_cnt[4];                     // per-group monotonic counters
// xi-GEMM operand tiles (pre-swizzled SW128 blocked-atom, bf16 split)
__device__ uint4 g_wbh[(size_t)4*24*8192];
__device__ uint4 g_wbl[(size_t)4*24*8192];
__device__ uint4 g_xah[(size_t)128*8192];
__device__ uint4 g_xal[(size_t)128*8192];

// ---------------- helpers ----------------
__device__ __forceinline__ float sigmoidf_(float x) {
    return 1.0f / (1.0f + __expf(-x));
}
__device__ __forceinline__ void red_add_release_gpu(unsigned* p, unsigned v) {
    asm volatile("red.release.gpu.add.u32 [%0], %1;" :: "l"(p), "r"(v) : "memory");
}
__device__ __forceinline__ unsigned ld_acquire_gpu(const unsigned* p) {
    unsigned v;
    asm volatile("ld.acquire.gpu.u32 %0, [%1];" : "=r"(v) : "l"(p) : "memory");
    return v;
}
__device__ __forceinline__ unsigned smem_u32(const void* p) {
    unsigned a;
    asm("{ .reg .u64 t; cvta.to.shared.u64 t, %1; cvt.u32.u64 %0, t; }"
        : "=r"(a) : "l"(p));
    return a;
}
__device__ __forceinline__ void mbar_init(unsigned a, unsigned cnt) {
    asm volatile("mbarrier.init.shared.b64 [%0], %1;" :: "r"(a), "r"(cnt) : "memory");
}
__device__ __forceinline__ void mbar_expect_tx(unsigned a, unsigned bytes) {
    asm volatile("mbarrier.arrive.expect_tx.shared.b64 _, [%0], %1;"
                 :: "r"(a), "r"(bytes) : "memory");
}
__device__ __forceinline__ void bulk_g2s(unsigned dst, const void* src,
                                         unsigned bytes, unsigned mbar) {
    asm volatile("cp.async.bulk.shared::cluster.global.mbarrier::complete_tx::bytes "
                 "[%0], [%1], %2, [%3];"
                 :: "r"(dst), "l"(src), "r"(bytes), "r"(mbar) : "memory");
}
__device__ __forceinline__ void mbar_wait_parity(unsigned a, unsigned phase) {
    unsigned done;
    asm volatile(
        "{\n\t.reg .pred p;\n\t"
        "mbarrier.try_wait.parity.acquire.cta.shared::cta.b64 p, [%1], %2;\n\t"
        "selp.b32 %0, 1, 0, p;\n\t}"
        : "=r"(done) : "r"(a), "r"(phase) : "memory");
    if (!done) {
        asm volatile(
            "{\n\t.reg .pred P1;\n\t"
            "WL_%=:\n\t"
            "mbarrier.try_wait.parity.acquire.cta.shared::cta.b64 P1, [%0], %1, 0x989680;\n\t"
            "@P1 bra.uni WD_%=;\n\t"
            "bra.uni WL_%=;\n\t"
            "WD_%=:\n\t}"
            :: "r"(a), "r"(phase) : "memory");
    }
}
// swizzled byte offset of (row 0..127, col 0..511 bf16) in a 128x512 tile
__device__ __forceinline__ uint32_t tile_off(int row, int col) {
    uint32_t byte = (uint32_t)(((row >> 3) + (col >> 6)*16)*1024
                               + (row & 7)*128 + (col & 63)*2);
    return byte ^ ((byte >> 3) & 0x70);
}
// within one staged 64-col block (col < 64), 128 rows
__device__ __forceinline__ uint32_t blk_off(int row, int col) {
    uint32_t byte = (uint32_t)(((row >> 3) << 10) + ((row & 7) << 7) + (col << 1));
    return byte ^ ((byte >> 3) & 0x70);
}
// 64-row x 128-col h plane chunk (16KB)
__device__ __forceinline__ uint32_t hplane_off(int row, int kl) {
    uint32_t byte = (uint32_t)((((row >> 3) + ((kl >> 6) << 3)) << 10)
                               + ((row & 7) << 7) + ((kl & 63) << 1));
    return byte ^ ((byte >> 3) & 0x70);
}
// 32-row x 512-col weight plane (32KB)
__device__ __forceinline__ uint32_t wplane_off(int row, int col) {
    uint32_t byte = (uint32_t)((((row >> 3) + ((col >> 6) << 2)) << 10)
                               + ((row & 7) << 7) + ((col & 63) << 1));
    return byte ^ ((byte >> 3) & 0x70);
}
__device__ __forceinline__ void split_bf16(float v, unsigned& h, unsigned& l) {
    __nv_bfloat16 hb = __float2bfloat16(v);
    float r = v - __bfloat162float(hb);
    __nv_bfloat16 lb = __float2bfloat16(r);
    h = (unsigned)__bfloat16_as_ushort(hb);
    l = (unsigned)__bfloat16_as_ushort(lb);
}
#define LDMATRIX_X4(r0, r1, r2, r3, addr) \
    asm volatile("ldmatrix.sync.aligned.m8n8.x4.shared.b16 {%0,%1,%2,%3}, [%4];" \
                 : "=r"(r0), "=r"(r1), "=r"(r2), "=r"(r3) : "r"(addr))
#define MMA_BF16(d, a, b) \
    asm volatile("mma.sync.aligned.m16n8k16.row.col.f32.bf16.bf16.f32 " \
                 "{%0,%1,%2,%3}, {%4,%5,%6,%7}, {%8,%9}, {%0,%1,%2,%3};" \
                 : "+f"((d)[0]), "+f"((d)[1]), "+f"((d)[2]), "+f"((d)[3]) \
                 : "r"((a)[0]), "r"((a)[1]), "r"((a)[2]), "r"((a)[3]), \
                   "r"((b)[0]), "r"((b)[1]))

// ---------------- prep: (B,T,K) -> [t][k][b], masked ----------------
__global__ void prep_kernel(const float* __restrict__ in, const int* __restrict__ len) {
    int idx = blockIdx.x * blockDim.x + threadIdx.x;
    if (idx >= TT*HH*BB) return;
    int b = idx & 63;
    int k = (idx >> 6) & 511;
    int t = idx >> 15;
    float v = 0.f;
    if (t < len[b]) v = in[((size_t)b*TT + t)*HH + k];
    g_xt[idx] = v;
}

// ------- pack W_hh into per-CTA swizzled split-bf16 B tiles [q32][k512] -------
__global__ void packwq_kernel(const float* __restrict__ weight) {
    int idx = blockIdx.x * blockDim.x + threadIdx.x;
    if (idx >= 4*128*32*64) return;
    int cu  = idx & 63;
    int row = (idx >> 6) & 31;
    int gq  = (idx >> 11) & 127;
    int l   = idx >> 18;
    unsigned h[8], lo[8];
    if (row < 20) {
        int hid = gq*4 + row/5;
        int g   = row % 5;
        const float* wsrc = weight + (size_t)l*LAYER_W_STRIDE + WHH_OFF;
        #pragma unroll
        for (int j = 0; j < 8; j++) {
            float v = wsrc[(size_t)(cu*8 + j)*G5 + g*512 + hid];
            split_bf16(v, h[j], lo[j]);
        }
    } else {
        #pragma unroll
        for (int j = 0; j < 8; j++) { h[j] = 0; lo[j] = 0; }
    }
    uint32_t off = wplane_off(row, cu*8);
    unsigned char* dst = g_whq + (size_t)(l*128 + gq)*65536;
    *(uint4*)(dst + off)         = make_uint4(h[0]|(h[1]<<16),  h[2]|(h[3]<<16),
                                              h[4]|(h[5]<<16),  h[6]|(h[7]<<16));
    *(uint4*)(dst + 32768 + off) = make_uint4(lo[0]|(lo[1]<<16), lo[2]|(lo[3]<<16),
                                              lo[4]|(lo[5]<<16), lo[6]|(lo[7]<<16));
}

// ---------------- pack W_ih^T into swizzled split-bf16 B tiles [n][k] ---------
__global__ void packwb_kernel(const float* __restrict__ weight) {
    int idx = blockIdx.x * blockDim.x + threadIdx.x;
    if (idx >= 4*24*128*64) return;
    int cu  = idx & 63;
    int row = (idx >> 6) & 127;
    int nt  = (idx >> 13) % 24;
    int l   = (idx >> 13) / 24;
    int g = nt*128 + row;
    const float* wsrc = weight + (size_t)l*LAYER_W_STRIDE;
    unsigned h[8], lo[8];
    #pragma unroll
    for (int j = 0; j < 8; j++) {
        float v = wsrc[(size_t)(cu*8 + j)*G6 + g];
        split_bf16(v, h[j], lo[j]);
    }
    size_t off = (size_t)(l*24 + nt)*8192 + (tile_off(row, cu*8) >> 4);
    g_wbh[off] = make_uint4(h[0]|(h[1]<<16),  h[2]|(h[3]<<16),
                            h[4]|(h[5]<<16),  h[6]|(h[7]<<16));
    g_wbl[off] = make_uint4(lo[0]|(lo[1]<<16), lo[2]|(lo[3]<<16),
                            lo[4]|(lo[5]<<16), lo[6]|(lo[7]<<16));
}

// ------- convert layer input -> swizzled split-bf16 A tiles [m][k] -----------
__global__ void conva_kernel(const float* __restrict__ xsrc,
                             const int* __restrict__ len, int rev) {
    int idx = blockIdx.x * blockDim.x + threadIdx.x;
    if (idx >= 128*128*64) return;
    int cu   = idx & 63;
    int row  = (idx >> 6) & 127;
    int tile = idx >> 13;
    int b = row & 63;
    int t = tile*2 + (row >> 6);
    if (rev) { int L = len[b]; if (t < L) t = L - 1 - t; }
    unsigned h[8], lo[8];
    #pragma unroll
    for (int j = 0; j < 8; j++) {
        float v = xsrc[((size_t)t*HH + cu*8 + j)*BB + b];
        split_bf16(v, h[j], lo[j]);
    }
    size_t off = (size_t)tile*8192 + (tile_off(row, cu*8) >> 4);
    g_xah[off] = make_uint4(h[0]|(h[1]<<16),  h[2]|(h[3]<<16),
                            h[4]|(h[5]<<16),  h[6]|(h[7]<<16));
    g_xal[off] = make_uint4(lo[0]|(lo[1]<<16), lo[2]|(lo[3]<<16),
                            lo[4]|(lo[5]<<16), lo[6]|(lo[7]<<16));
}

// ---------------- bf16-split mma.sync xi GEMM (3-stage pipeline) -------------
__global__ __launch_bounds__(256)
void gemm_mma_kernel(const uint8_t* __restrict__ Ah, const uint8_t* __restrict__ Al,
                     const uint8_t* __restrict__ Bh, const uint8_t* __restrict__ Bl,
                     float* __restrict__ XI)
{
    extern __shared__ __align__(1024) uint8_t smg[];
    int tid = threadIdx.x;
    int lane = tid & 31, wid = tid >> 5;
    int wm = wid & 3, wn = wid >> 2;
    int mt = blockIdx.x, nt = blockIdx.y;
    unsigned sm = smem_u32(smg);
    unsigned mbf = sm + 196608u;

    if (tid == 0) {
        mbar_init(mbf, 1); mbar_init(mbf + 8, 1); mbar_init(mbf + 16, 1);
        asm volatile("fence.proxy.async.shared::cta;" ::: "memory");
    }
    __syncthreads();

    const uint8_t* aH = Ah + (size_t)mt*131072;
    const uint8_t* aL = Al + (size_t)mt*131072;
    const uint8_t* bH = Bh + (size_t)nt*131072;
    const uint8_t* bL = Bl + (size_t)nt*131072;

    if (tid == 0) {
        #pragma unroll
        for (int s = 0; s < 3; s++) {
            unsigned sb = sm + (unsigned)s*65536u;
            mbar_expect_tx(mbf + 8*s, 65536u);
            bulk_g2s(sb,           aH + s*16384, 16384u, mbf + 8*s);
            bulk_g2s(sb + 16384u,  aL + s*16384, 16384u, mbf + 8*s);
            bulk_g2s(sb + 32768u,  bH + s*16384, 16384u, mbf + 8*s);
            bulk_g2s(sb + 49152u,  bL + s*16384, 16384u, mbf + 8*s);
        }
    }

    float acc[2][8][4];
    #pragma unroll
    for (int mi = 0; mi < 2; mi++)
        #pragma unroll
        for (int nj = 0; nj < 8; nj++)
            #pragma unroll
            for (int q = 0; q < 4; q++) acc[mi][nj][q] = 0.f;

    int r  = lane & 7;
    int ts = lane >> 3;
    int arow0 = wm*32 + r + ((ts & 1) << 3);
    int akadd = (ts >> 1) << 3;
    int brow0 = wn*64 + r + ((ts >> 1) << 3);
    int bkadd = (ts & 1) << 3;

    for (int s = 0; s < 8; s++) {
        int p = s % 3;
        unsigned ph = (unsigned)((s / 3) & 1);
        mbar_wait_parity(mbf + 8*p, ph);
        unsigned sb  = sm + (unsigned)p*65536u;
        unsigned sAh = sb, sAl = sb + 16384u;
        unsigned sBh = sb + 32768u, sBl = sb + 49152u;

        #pragma unroll
        for (int j = 0; j < 4; j++) {
            int kc = j*16 + akadd;
            uint32_t ah0[4], ah1[4], al0[4], al1[4];
            {
                unsigned o0 = blk_off(arow0,      kc);
                unsigned o1 = blk_off(arow0 + 16, kc);
                LDMATRIX_X4(ah0[0], ah0[1], ah0[2], ah0[3], sAh + o0);
                LDMATRIX_X4(ah1[0], ah1[1], ah1[2], ah1[3], sAh + o1);
                LDMATRIX_X4(al0[0], al0[1], al0[2], al0[3], sAl + o0);
                LDMATRIX_X4(al1[0], al1[1], al1[2], al1[3], sAl + o1);
            }
            int kb = j*16 + bkadd;
            uint32_t bh[8][2], bl[8][2];
            #pragma unroll
            for (int p4 = 0; p4 < 4; p4++) {
                unsigned ob = blk_off(brow0 + p4*16, kb);
                LDMATRIX_X4(bh[2*p4][0], bh[2*p4][1], bh[2*p4+1][0], bh[2*p4+1][1],
                            sBh + ob);
                LDMATRIX_X4(bl[2*p4][0], bl[2*p4][1], bl[2*p4+1][0], bl[2*p4+1][1],
                            sBl + ob);
            }
            #pragma unroll
            for (int nj = 0; nj < 8; nj++) {
                MMA_BF16(acc[0][nj], ah0, bh[nj]);
                MMA_BF16(acc[1][nj], ah1, bh[nj]);
                MMA_BF16(acc[0][nj], ah0, bl[nj]);
                MMA_BF16(acc[1][nj], ah1, bl[nj]);
                MMA_BF16(acc[0][nj], al0, bh[nj]);
                MMA_BF16(acc[1][nj], al1, bh[nj]);
            }
        }
        __syncthreads();
        if (tid == 0 && s + 3 < 8) {
            int s2 = s + 3;
            mbar_expect_tx(mbf + 8*p, 65536u);
            bulk_g2s(sb,          aH + s2*16384, 16384u, mbf + 8*p);
            bulk_g2s(sb + 16384u, aL + s2*16384, 16384u, mbf + 8*p);
            bulk_g2s(sb + 32768u, bH + s2*16384, 16384u, mbf + 8*p);
            bulk_g2s(sb + 49152u, bL + s2*16384, 16384u, mbf + 8*p);
        }
    }

    int g4 = lane >> 2, t4 = lane & 3;
    #pragma unroll
    for (int mi = 0; mi < 2; mi++) {
        #pragma unroll
        for (int half = 0; half < 2; half++) {
            int m = mt*128 + wm*32 + mi*16 + g4 + half*8;
            int t = m >> 6, b = m & 63;
            float* xo = XI + ((size_t)t*G6 + nt*128 + wn*64 + t4*2)*64 + b;
            #pragma unroll
            for (int nj = 0; nj < 8; nj++) {
                xo[(size_t)(nj*8)*64]       = acc[mi][nj][half*2];
                xo[(size_t)(nj*8 + 1)*64]   = acc[mi][nj][half*2 + 1];
            }
        }
    }
}

// ---------------- persistent per-layer recurrence (tensor-core math) ---------
// R14 skeleton; hi/lo sub-chunk staging: each 32KB chunk -> hi 16KB + lo 16KB
// with separate mbarriers. Consumer: wait hi -> AhBh + AhBl (Bh frags kept in
// regs) -> wait lo -> AlBh. Compute starts one 16KB TMA earlier per chunk.
__global__ __launch_bounds__(288)
void lstm_layer_kernel(const float* __restrict__ xi_base,
                       const unsigned char* __restrict__ wq,
                       const float* __restrict__ bias,
                       const int*   __restrict__ len,
                       unsigned char* __restrict__ hbuf0,
                       unsigned char* __restrict__ hbuf1,
                       float* __restrict__ y,
                       int rev)
{
    extern __shared__ float smf[];
    int tid = threadIdx.x;
    int hid0 = blockIdx.x * 4;
    int grp  = blockIdx.x >> 5;

    unsigned smbase = smem_u32(smf);
    unsigned smW    = smbase + OWQ_F*4;
    unsigned smH    = smbase + OH_F*4;
    unsigned mbar0  = smbase + OFF_MBAR_B;   // 8 mbars: [ch].hi @16ch, [ch].lo @16ch+8

    int lane = tid & 31, wid = tid >> 5;
    int wm = wid & 3, wn = (wid >> 2) & 1;
    int hl_o = (tid >> 6) & 3;
    int b_o  = tid & 63;
    int hid_o = hid0 + hl_o;

    if (tid < 256) {
        const uint4* ws = (const uint4*)(wq + (size_t)blockIdx.x*65536);
        uint4* wd = (uint4*)smf;
        #pragma unroll
        for (int i = 0; i < 16; i++) wd[tid + i*256] = ws[tid + i*256];
    }
    if (tid == 256) {
        #pragma unroll
        for (int c = 0; c < 8; c++) mbar_init(mbar0 + 8*c, 1);
        asm volatile("fence.proxy.async.shared::cta;" ::: "memory");
    }

    float bval[5] = {0.f, 0.f, 0.f, 0.f, 0.f};
    int L = 0;
    float xiv[6] = {0.f, 0.f, 0.f, 0.f, 0.f, 0.f};
    if (tid < 256) {
        #pragma unroll
        for (int g = 0; g < 5; g++) bval[g] = bias[g*512 + hid_o];
        L = len[b_o];
        #pragma unroll
        for (int g = 0; g < 6; g++)
            xiv[g] = __ldcs(xi_base + (size_t)(g*512 + hid_o)*BB + b_o);
    }
    float c = 0.0f;

    unsigned char* hin  = hbuf0;
    unsigned char* hout = hbuf1;

    int r  = lane & 7;
    int ts = lane >> 3;
    int arow = wm*16 + r + ((ts & 1) << 3);
    int ak   = (ts >> 1) << 3;
    int brow = wn*16 + r + ((ts >> 1) << 3);
    int bk   = (ts & 1) << 3;

    __syncthreads();

    if (tid == 256) {
        #pragma unroll
        for (int ch = 0; ch < 4; ch++) {
            mbar_expect_tx(mbar0 + 16*ch, 16384u);
            bulk_g2s(smH + ch*32768u, hin + ch*32768, 16384u, mbar0 + 16*ch);
            mbar_expect_tx(mbar0 + 16*ch + 8, 16384u);
            bulk_g2s(smH + ch*32768u + 16384u, hin + ch*32768 + 16384, 16384u,
                     mbar0 + 16*ch + 8);
        }
    }

    for (int s = 0; s < TT; s++) {
        unsigned phase = (unsigned)(s & 1);

        if (tid < 256) {
            float acc[2][4];
            #pragma unroll
            for (int nj = 0; nj < 2; nj++)
                #pragma unroll
                for (int q = 0; q < 4; q++) acc[nj][q] = 0.f;

            #pragma unroll
            for (int ch = 0; ch < 4; ch++) {
                unsigned sAh = smH + ch*32768u;
                unsigned sAl = sAh + 16384u;
                uint32_t bhsv[8][2][2];

                mbar_wait_parity(mbar0 + 16*ch, phase);       // hi plane ready
                #pragma unroll
                for (int j = 0; j < 8; j++) {
                    unsigned ao = hplane_off(arow, j*16 + ak);
                    uint32_t ah[4];
                    LDMATRIX_X4(ah[0], ah[1], ah[2], ah[3], sAh + ao);
                    int kg = ch*128 + j*16 + bk;
                    unsigned bo = wplane_off(brow, kg);
                    uint32_t bl[2][2];
                    LDMATRIX_X4(bhsv[j][0][0], bhsv[j][0][1],
                                bhsv[j][1][0], bhsv[j][1][1], smW + bo);
                    LDMATRIX_X4(bl[0][0], bl[0][1], bl[1][0], bl[1][1],
                                smW + 32768u + bo);
                    #pragma unroll
                    for (int nj = 0; nj < 2; nj++) {
                        MMA_BF16(acc[nj], ah, bhsv[j][nj]);
                        MMA_BF16(acc[nj], ah, bl[nj]);
                    }
                }
                mbar_wait_parity(mbar0 + 16*ch + 8, phase);   // lo plane ready
                #pragma unroll
                for (int j = 0; j < 8; j++) {
                    unsigned ao = hplane_off(arow, j*16 + ak);
                    uint32_t al[4];
                    LDMATRIX_X4(al[0], al[1], al[2], al[3], sAl + ao);
                    #pragma unroll
                    for (int nj = 0; nj < 2; nj++)
                        MMA_BF16(acc[nj], al, bhsv[j][nj]);
                }
            }

            float* db = smf + OD_F;
            int drow = wm*16 + (lane >> 2);
            int dcol = wn*16 + (lane & 3)*2;
            #pragma unroll
            for (int nj = 0; nj < 2; nj++) {
                db[drow*34 + dcol + nj*8]       = acc[nj][0];
                db[drow*34 + dcol + nj*8 + 1]   = acc[nj][1];
                db[(drow+8)*34 + dcol + nj*8]   = acc[nj][2];
                db[(drow+8)*34 + dcol + nj*8+1] = acc[nj][3];
            }
        }
        __syncthreads();                              // sync A

        float hn = 0.f;
        if (tid < 256) {
            const float* db = smf + OD_F + b_o*34 + hl_o*5;
            float gv[5];
            #pragma unroll
            for (int g = 0; g < 5; g++) gv[g] = xiv[g] + bval[g] + db[g];

            float ig = sigmoidf_(gv[0]);
            float fg = sigmoidf_(gv[1]);
            float gc = tanhf(gv[2]);
            float og = sigmoidf_(gv[3]);
            float rg = sigmoidf_(gv[4]);
            float lin = xiv[5];

            float cn;
            if (s < L) {
                cn = fg*c + ig*gc;
                hn = rg*(og*tanhf(cn)) + (1.f - rg)*lin;
            } else {
                cn = 0.f; hn = 0.f;
            }
            c = cn;
            unsigned hi16, lo16;
            split_bf16(hn, hi16, lo16);
            int chn = hid_o >> 7, kl = hid_o & 127;
            uint32_t loc = hplane_off(b_o, kl);
            *(uint16_t*)(hout + chn*32768 + loc)          = (uint16_t)hi16;
            *(uint16_t*)(hout + chn*32768 + 16384 + loc)  = (uint16_t)lo16;
        }
        __syncthreads();                              // sync B

        int dst = rev ? ((s < L) ? (L - 1 - s) : s) : s;

        if (s != TT-1) {
            if (tid == 0)
                red_add_release_gpu(&g_cnt[grp], 1u);

            if (tid < 256) {
                y[((size_t)dst*HH + hid_o)*BB + b_o] = hn;
                const float* xs = xi_base + (size_t)(s+1)*G6*BB;
                #pragma unroll
                for (int g = 0; g < 6; g++)
                    xiv[g] = __ldcs(xs + (size_t)(g*512 + hid_o)*BB + b_o);
            }

            if (tid == 256) {
                const unsigned char* hsrc = hout;
                unsigned target = 32u * (unsigned)(s + 1);
                #pragma unroll
                for (int ch = 0; ch < 4; ch++) {
                    while (ld_acquire_gpu(&g_cnt[ch]) < target) __nanosleep(32);
                    mbar_expect_tx(mbar0 + 16*ch, 16384u);
                    bulk_g2s(smH + ch*32768u, hsrc + ch*32768, 16384u,
                             mbar0 + 16*ch);
                    mbar_expect_tx(mbar0 + 16*ch + 8, 16384u);
                    bulk_g2s(smH + ch*32768u + 16384u, hsrc + ch*32768 + 16384,
                             16384u, mbar0 + 16*ch + 8);
                }
            }
        } else if (tid < 256) {
            y[((size_t)dst*HH + hid_o)*BB + b_o] = hn;
        }

        unsigned char* tmp = hin; hin = hout; hout = tmp;
    }
}

// ---------------- final: [t][k][b] -> (B,T,K) ----------------
__global__ void out_kernel(const float* __restrict__ xt, float* __restrict__ out) {
    int idx = blockIdx.x * blockDim.x + threadIdx.x;
    if (idx >= TT*HH*BB) return;
    int k = idx & 511;
    int t = (idx >> 9) & 255;
    int b = idx >> 17;
    out[idx] = xt[((size_t)t*HH + k)*BB + b];
}

// ---------------- launch ----------------
extern "C" void kernel_launch(void* const* d_in, const int* in_sizes, int n_in,
                              void* d_out, int out_size)
{
    const float* inputs = nullptr;
    const float* weight = nullptr;
    const float* biasp  = nullptr;
    const int*   len    = nullptr;
    for (int i = 0; i < n_in; i++) {
        switch (in_sizes[i]) {
            case TT*BB*HH:  inputs = (const float*)d_in[i]; break;  // 8388608
            case 11534336:  weight = (const float*)d_in[i]; break;
            case 4*G5:      biasp  = (const float*)d_in[i]; break;  // 10240
            case BB:        len    = (const int*)  d_in[i]; break;  // 64
        }
    }

    float *pxt, *pyt, *pxi;
    unsigned char *phb0, *phb1, *pwhq;
    unsigned* pcnt;
    uint4 *pwbh, *pwbl, *pxah, *pxal;
    cudaGetSymbolAddress((void**)&pxt,  g_xt);
    cudaGetSymbolAddress((void**)&pyt,  g_yt);
    cudaGetSymbolAddress((void**)&pxi,  g_xi);
    cudaGetSymbolAddress((void**)&phb0, g_hb0);
    cudaGetSymbolAddress((void**)&phb1, g_hb1);
    cudaGetSymbolAddress((void**)&pwhq, g_whq);
    cudaGetSymbolAddress((void**)&pcnt, g_cnt);
    cudaGetSymbolAddress((void**)&pwbh, g_wbh);
    cudaGetSymbolAddress((void**)&pwbl, g_wbl);
    cudaGetSymbolAddress((void**)&pxah, g_xah);
    cudaGetSymbolAddress((void**)&pxal, g_xal);

    cudaFuncSetAttribute(lstm_layer_kernel,
                         cudaFuncAttributeMaxDynamicSharedMemorySize, SMEM_LSTM);
    cudaFuncSetAttribute(gemm_mma_kernel,
                         cudaFuncAttributeMaxDynamicSharedMemorySize, SMEM_GMM);

    prep_kernel<<<(TT*HH*BB + 255)/256, 256>>>(inputs, len);
    packwq_kernel<<<(4*128*32*64)/256, 256>>>(weight);
    packwb_kernel<<<(4*24*128*64)/256, 256>>>(weight);

    float* xin  = pxt;
    float* yout = pyt;
    for (int l = 0; l < 4; l++) {
        int rev = l & 1;
        conva_kernel<<<(128*128*64)/256, 256>>>(xin, len, rev);
        gemm_mma_kernel<<<dim3(128, 24), 256, SMEM_GMM>>>(
            (const uint8_t*)pxah, (const uint8_t*)pxal,
            (const uint8_t*)(pwbh + (size_t)l*24*8192),
            (const uint8_t*)(pwbl + (size_t)l*24*8192),
            pxi);
        cudaMemsetAsync(phb0, 0, 4*32768);
        cudaMemsetAsync(pcnt, 0, 4*sizeof(unsigned));
        lstm_layer_kernel<<<NCTA, 288, SMEM_LSTM>>>(
            pxi, pwhq + (size_t)l*128*65536, biasp + (size_t)l*G5,
            len, phb0, phb1, yout, rev);
        float* tmp = xin; xin = yout; yout = tmp;
    }
    out_kernel<<<(TT*HH*BB + 255)/256, 256>>>(xin, (float*)d_out);
}